// round 13
// baseline (speedup 1.0000x reference)
#include <cuda_runtime.h>
#include <cuda_fp16.h>
#include <math.h>

#define NB 148
#define NT 1024
#define NMAX 50000
#define EMAX 1600000

typedef unsigned long long u64;

// ---------------- scratch (device globals) ----------------
__device__ __half d_h0h[(size_t)NMAX * 64];   // emb out (pre-scaled by dinv), fp16
__device__ __half d_l1h[(size_t)NMAX * 128];  // c1 out (pre-scaled), fp16
__device__ __half d_l2h[(size_t)NMAX * 128];  // c2 out = final features, fp16
__device__ __half d_gh [(size_t)NMAX * 64];   // bond projection, fp16
__device__ __half d_t12h[(size_t)NMAX * 128]; // [t1h | t1e] fp16
__device__ __half d_t2x[(size_t)NMAX * 64];   // [t2h | t2e] fp16
__device__ float  d_b2c[64];                  // [hb2 | eb2]
__device__ float  d_dinv[NMAX];
__device__ int    d_deg[NMAX];
__device__ int    d_off[NMAX + 1];
__device__ int    d_cur[NMAX];
__device__ int    d_srcs[EMAX];
__device__ int    d_bsum[NB];
__device__ double d_pb[NB];
__device__ double d_pt[NB];
__device__ unsigned int g_bar;               // monotonic across replays

// ---------------- grid barrier ----------------
__device__ __forceinline__ void gbar() {
    __syncthreads();
    if (threadIdx.x == 0) {
        __threadfence();
        unsigned int old = atomicAdd(&g_bar, 1u);
        unsigned int target = (old / NB + 1u) * NB;
        while (*((volatile unsigned int*)&g_bar) < target) { }
        __threadfence();
    }
    __syncthreads();
}

__device__ __forceinline__ float2 h22f2(unsigned u) {
    __half2 h = *reinterpret_cast<__half2*>(&u);
    return __half22float2(h);
}

__device__ __forceinline__ unsigned smem_u32(const void* p) {
    return (unsigned)__cvta_generic_to_shared(p);
}

__device__ __forceinline__ void mma16816(float* d,
                                         unsigned a0, unsigned a1, unsigned a2, unsigned a3,
                                         unsigned b0, unsigned b1) {
    asm volatile(
        "mma.sync.aligned.m16n8k16.row.col.f32.f16.f16.f32 "
        "{%0,%1,%2,%3}, {%4,%5,%6,%7}, {%8,%9}, {%0,%1,%2,%3};"
        : "+f"(d[0]), "+f"(d[1]), "+f"(d[2]), "+f"(d[3])
        : "r"(a0), "r"(a1), "r"(a2), "r"(a3), "r"(b0), "r"(b1));
}

// ---------------- tensor-core multi-output GEMM ----------------
// All NS weight sets staged ONCE per pass; X staged once per tile.
// MODE: 0 = copy fp16 rows, 1 = convert fp32 rows, 2 = aggregate (GCN) from fp16 table with dinv.
// flags: 1=relu, 2=scale(dinv), 4=fp16 out, 8=block-diag W (Ws upper-left 32x64, Ws2 lower-right 32x64)
template <int K, int MODE, int NS>
__device__ __forceinline__ void gemm_multi(
    const void* xin,
    const float* const* Ws, const float* const* Ws2, const float* const* Bs,
    void* const* Os, const int* osts, const unsigned* flg,
    int n, __half* sWh, __half* sXh) {

    const int C = K / 8;          // 16B chunks per X row
    const int KP = K + 8;         // padded W row (halves)
    const int WSZ = 64 * KP;      // halves per weight spec
    int tid = threadIdx.x;
    int w = tid >> 5, lane = tid & 31;
    int node0 = (w & 7) * 16;     // 8 node groups x 16
    int o0 = (w >> 3) * 16;       // 4 out groups x 16
    int g = lane >> 2, t = lane & 3;
    int ntiles = (n + 127) >> 7;
    unsigned sx_base = smem_u32(sXh);

    // ---- stage ALL weight specs once ----
    #pragma unroll
    for (int s = 0; s < NS; s++) {
        __half* sw = sWh + s * WSZ;
        if (flg[s] & 8u) {
            const float* Wh = Ws[s];
            const float* We = Ws2[s];
            for (int idx = tid; idx < 64 * (KP / 2); idx += NT) {
                int o = idx / (KP / 2), w2 = idx - o * (KP / 2);
                unsigned val = 0u;
                if (o < 32) {
                    if (w2 < 32) {
                        float2 v = *(const float2*)(Wh + o * 64 + w2 * 2);
                        __half2 h = __floats2half2_rn(v.x, v.y);
                        val = *reinterpret_cast<unsigned*>(&h);
                    }
                } else {
                    if (w2 >= 32 && w2 < 64) {
                        float2 v = *(const float2*)(We + (o - 32) * 64 + (w2 - 32) * 2);
                        __half2 h = __floats2half2_rn(v.x, v.y);
                        val = *reinterpret_cast<unsigned*>(&h);
                    }
                }
                *(unsigned*)(sw + o * KP + w2 * 2) = val;
            }
        } else {
            const float* Wp = Ws[s];
            for (int idx = tid; idx < 64 * (K / 2); idx += NT) {
                int o = idx / (K / 2), k2 = idx - o * (K / 2);
                float2 wv = *(const float2*)(Wp + o * K + k2 * 2);
                __half2 h = __floats2half2_rn(wv.x, wv.y);
                *(unsigned*)(sw + o * KP + k2 * 2) = *reinterpret_cast<unsigned*>(&h);
            }
        }
    }
    __syncthreads();

    for (int tile = blockIdx.x; tile < ntiles; tile += NB) {
        int base = tile << 7;
        int nn_max = n - base; if (nn_max > 128) nn_max = 128;
        __syncthreads();                              // prior tile's sX readers done
        // ---- stage X (once per tile) ----
        if (MODE == 1) {
            const float* xf = (const float*)xin;
            for (int idx = tid; idx < 128 * C; idx += NT) {
                int nn = idx / C, c = idx - nn * C;
                uint4 q;
                if (nn < nn_max) {
                    const float* p = xf + (size_t)(base + nn) * K + c * 8;
                    float4 v0 = *(const float4*)p;
                    float4 v1 = *(const float4*)(p + 4);
                    __half2 h0 = __floats2half2_rn(v0.x, v0.y);
                    __half2 h1 = __floats2half2_rn(v0.z, v0.w);
                    __half2 h2 = __floats2half2_rn(v1.x, v1.y);
                    __half2 h3 = __floats2half2_rn(v1.z, v1.w);
                    q.x = *reinterpret_cast<unsigned*>(&h0);
                    q.y = *reinterpret_cast<unsigned*>(&h1);
                    q.z = *reinterpret_cast<unsigned*>(&h2);
                    q.w = *reinterpret_cast<unsigned*>(&h3);
                } else { q = make_uint4(0, 0, 0, 0); }
                *(uint4*)(sXh + nn * K + ((c ^ (nn & 7)) << 3)) = q;
            }
        } else if (MODE == 0) {
            const __half* xh = (const __half*)xin;
            for (int idx = tid; idx < 128 * C; idx += NT) {
                int nn = idx / C, c = idx - nn * C;
                uint4 q = (nn < nn_max)
                    ? *(const uint4*)(xh + (size_t)(base + nn) * K + c * 8)
                    : make_uint4(0, 0, 0, 0);
                *(uint4*)(sXh + nn * K + ((c ^ (nn & 7)) << 3)) = q;
            }
        } else {
            // MODE 2: GCN aggregation from fp16 table; warp per node (4 nodes/warp)
            const __half* tbl = (const __half*)xin;
            const int NPL = K / 32;                   // halves per lane: 4 (K=128) or 2 (K=64)
            int cc = lane * NPL;
            #pragma unroll
            for (int i = 0; i < 4; i++) {
                int nn = w * 4 + i;
                int node = base + nn;
                float a0 = 0.f, a1 = 0.f, a2 = 0.f, a3 = 0.f;
                if (node < n) {
                    if (NPL == 4) {
                        uint2 us = *(const uint2*)(tbl + (size_t)node * K + cc);
                        float2 f0 = h22f2(us.x), f1 = h22f2(us.y);
                        a0 = f0.x; a1 = f0.y; a2 = f1.x; a3 = f1.y;
                    } else {
                        unsigned us = *(const unsigned*)(tbl + (size_t)node * K + cc);
                        float2 f0 = h22f2(us);
                        a0 = f0.x; a1 = f0.y;
                    }
                    int j0 = d_off[node], j1 = d_off[node + 1];
                    int j = j0;
                    for (; j + 3 < j1; j += 4) {
                        int i0 = d_srcs[j], i1 = d_srcs[j + 1];
                        int i2 = d_srcs[j + 2], i3 = d_srcs[j + 3];
                        if (NPL == 4) {
                            uint2 u0 = *(const uint2*)(tbl + (size_t)i0 * K + cc);
                            uint2 u1 = *(const uint2*)(tbl + (size_t)i1 * K + cc);
                            uint2 u2 = *(const uint2*)(tbl + (size_t)i2 * K + cc);
                            uint2 u3 = *(const uint2*)(tbl + (size_t)i3 * K + cc);
                            float2 p0 = h22f2(u0.x), p1 = h22f2(u0.y);
                            float2 q0 = h22f2(u1.x), q1 = h22f2(u1.y);
                            float2 r0 = h22f2(u2.x), r1 = h22f2(u2.y);
                            float2 s0 = h22f2(u3.x), s1 = h22f2(u3.y);
                            a0 += (p0.x + q0.x) + (r0.x + s0.x);
                            a1 += (p0.y + q0.y) + (r0.y + s0.y);
                            a2 += (p1.x + q1.x) + (r1.x + s1.x);
                            a3 += (p1.y + q1.y) + (r1.y + s1.y);
                        } else {
                            unsigned u0 = *(const unsigned*)(tbl + (size_t)i0 * K + cc);
                            unsigned u1 = *(const unsigned*)(tbl + (size_t)i1 * K + cc);
                            unsigned u2 = *(const unsigned*)(tbl + (size_t)i2 * K + cc);
                            unsigned u3 = *(const unsigned*)(tbl + (size_t)i3 * K + cc);
                            float2 p0 = h22f2(u0), q0 = h22f2(u1);
                            float2 r0 = h22f2(u2), s0 = h22f2(u3);
                            a0 += (p0.x + q0.x) + (r0.x + s0.x);
                            a1 += (p0.y + q0.y) + (r0.y + s0.y);
                        }
                    }
                    for (; j < j1; j++) {
                        int i0 = d_srcs[j];
                        if (NPL == 4) {
                            uint2 u0 = *(const uint2*)(tbl + (size_t)i0 * K + cc);
                            float2 p0 = h22f2(u0.x), p1 = h22f2(u0.y);
                            a0 += p0.x; a1 += p0.y; a2 += p1.x; a3 += p1.y;
                        } else {
                            unsigned u0 = *(const unsigned*)(tbl + (size_t)i0 * K + cc);
                            float2 p0 = h22f2(u0);
                            a0 += p0.x; a1 += p0.y;
                        }
                    }
                    float dv = d_dinv[node];
                    a0 *= dv; a1 *= dv; a2 *= dv; a3 *= dv;
                }
                int chunk = cc >> 3;
                __half* dstp = sXh + nn * K + ((chunk ^ (nn & 7)) << 3) + (cc & 7);
                __half2 h0 = __floats2half2_rn(a0, a1);
                if (NPL == 4) {
                    __half2 h1 = __floats2half2_rn(a2, a3);
                    uint2 uu;
                    uu.x = *reinterpret_cast<unsigned*>(&h0);
                    uu.y = *reinterpret_cast<unsigned*>(&h1);
                    *(uint2*)dstp = uu;
                } else {
                    *(unsigned*)dstp = *reinterpret_cast<unsigned*>(&h0);
                }
            }
        }
        __syncthreads();

        // ---- compute all specs on the staged tile ----
        #pragma unroll
        for (int s = 0; s < NS; s++) {
            const __half* sw = sWh + s * WSZ;
            unsigned f = flg[s];
            const float* Bp = Bs[s];
            float ba0 = Bp[o0 + t * 2],     ba1 = Bp[o0 + t * 2 + 1];
            float bb0 = Bp[o0 + 8 + t * 2], bb1 = Bp[o0 + 8 + t * 2 + 1];
            float d0[4] = {ba0, ba1, ba0, ba1};
            float d1[4] = {bb0, bb1, bb0, bb1};

            int row = node0 + (lane & 15);
            #pragma unroll
            for (int ks = 0; ks < K / 16; ks++) {
                int chunk = ks * 2 + (lane >> 4);
                unsigned addr = sx_base + (unsigned)(row * (K * 2) + ((chunk ^ (row & 7)) << 4));
                unsigned a0, a1, a2, a3;
                asm volatile("ldmatrix.sync.aligned.m8n8.x4.shared.b16 {%0,%1,%2,%3}, [%4];"
                             : "=r"(a0), "=r"(a1), "=r"(a2), "=r"(a3) : "r"(addr));
                const __half* wb = sw + ks * 16 + t * 2;
                unsigned b00 = *(const unsigned*)(wb + (o0 + g) * KP);
                unsigned b01 = *(const unsigned*)(wb + (o0 + g) * KP + 8);
                unsigned b10 = *(const unsigned*)(wb + (o0 + 8 + g) * KP);
                unsigned b11 = *(const unsigned*)(wb + (o0 + 8 + g) * KP + 8);
                mma16816(d0, a0, a1, a2, a3, b00, b01);
                mma16816(d1, a0, a1, a2, a3, b10, b11);
            }

            int ost = osts[s];
            int nl0 = node0 + g, nl1 = nl0 + 8;
            #pragma unroll
            for (int half_ = 0; half_ < 2; half_++) {
                int nl = half_ ? nl1 : nl0;
                if (nl < nn_max) {
                    int node = base + nl;
                    float v0 = half_ ? d0[2] : d0[0];
                    float v1 = half_ ? d0[3] : d0[1];
                    float v2 = half_ ? d1[2] : d1[0];
                    float v3 = half_ ? d1[3] : d1[1];
                    if (f & 1u) {
                        v0 = fmaxf(v0, 0.f); v1 = fmaxf(v1, 0.f);
                        v2 = fmaxf(v2, 0.f); v3 = fmaxf(v3, 0.f);
                    }
                    if (f & 2u) {
                        float sc = d_dinv[node];
                        v0 *= sc; v1 *= sc; v2 *= sc; v3 *= sc;
                    }
                    if (f & 4u) {
                        __half* op = (__half*)Os[s] + (size_t)node * ost;
                        __half2 h0 = __floats2half2_rn(v0, v1);
                        __half2 h1 = __floats2half2_rn(v2, v3);
                        *(unsigned*)(op + o0 + t * 2)     = *reinterpret_cast<unsigned*>(&h0);
                        *(unsigned*)(op + o0 + 8 + t * 2) = *reinterpret_cast<unsigned*>(&h1);
                    } else {
                        float* op = (float*)Os[s] + (size_t)node * ost;
                        *(float2*)(op + o0 + t * 2)     = make_float2(v0, v1);
                        *(float2*)(op + o0 + 8 + t * 2) = make_float2(v2, v3);
                    }
                }
            }
        }
    }
}

// ---------------- the megakernel ----------------
extern __shared__ float smem_buf[];

__global__ __launch_bounds__(NT, 1) void mega(
    const float* __restrict__ x, const int* __restrict__ src, const int* __restrict__ dst,
    const float* __restrict__ pos,
    const float* __restrict__ emb_w, const float* __restrict__ emb_b,
    const float* __restrict__ c1_w, const float* __restrict__ c1_b,
    const float* __restrict__ c2_w, const float* __restrict__ c2_b,
    const float* __restrict__ bw1, const float* __restrict__ bb1,
    const float* __restrict__ bw2, const float* __restrict__ bb2,
    const float* __restrict__ hw1, const float* __restrict__ hb1,
    const float* __restrict__ hw2, const float* __restrict__ hb2,
    const float* __restrict__ hw3, const float* __restrict__ hb3,
    const float* __restrict__ ew1, const float* __restrict__ eb1,
    const float* __restrict__ ew2, const float* __restrict__ eb2,
    const float* __restrict__ ew3, const float* __restrict__ eb3,
    float* __restrict__ out, int n, int e) {

    __shared__ float s_red[32];
    __shared__ int   s_ired[32];
    __shared__ int   s_all[NB];
    __shared__ int   s_base;
    __shared__ float s3w[64];

    int tid = threadIdx.x, bid = blockIdx.x;
    int lane = tid & 31, wid = tid >> 5;
    int gt = bid * NT + tid;
    const int GSTR = NB * NT;
    __half* sWh = (__half*)smem_buf;                    // up to 3 specs x [64][K+8]
    __half* sXh = (__half*)((char*)smem_buf + 52224);   // [128][K] fp16 swizzled

    // ---- S0: zero degrees + build combined bias ----
    for (int i = gt; i < n; i += GSTR) d_deg[i] = 0;
    if (bid == 0 && tid < 64) d_b2c[tid] = (tid < 32) ? hb2[tid] : eb2[tid - 32];
    gbar();

    // ---- S1: count in-degrees ----
    for (int i = gt; i < e; i += GSTR) atomicAdd(&d_deg[dst[i]], 1);
    gbar();

    // ---- S2a: per-block chunk sums ----
    int chunk = (n + NB - 1) / NB;
    int lo = bid * chunk;
    int len = n - lo; if (len < 0) len = 0; if (len > chunk) len = chunk;
    int v = (tid < len) ? d_deg[lo + tid] : 0;
    {
        int wv = v;
        #pragma unroll
        for (int st = 16; st > 0; st >>= 1) wv += __shfl_down_sync(0xffffffffu, wv, st);
        if (lane == 0) s_ired[wid] = wv;
        __syncthreads();
        if (tid < 32) {
            int s = s_ired[tid];
            #pragma unroll
            for (int st = 16; st > 0; st >>= 1) s += __shfl_down_sync(0xffffffffu, s, st);
            if (tid == 0) d_bsum[bid] = s;
        }
    }
    gbar();

    // ---- S2c: base + local exclusive scan -> off/cur/dinv ----
    if (tid < NB) s_all[tid] = d_bsum[tid];
    __syncthreads();
    if (tid == 0) {
        int b = 0;
        for (int j = 0; j < bid; j++) b += s_all[j];
        s_base = b;
        if (bid == NB - 1) d_off[n] = b + s_all[NB - 1];
    }
    {
        int* a = (int*)smem_buf;
        a[tid] = v;
        __syncthreads();
        for (int st = 1; st < NT; st <<= 1) {
            int t = (tid >= st) ? a[tid - st] : 0;
            __syncthreads();
            a[tid] += t;
            __syncthreads();
        }
        int excl = a[tid] - v;
        if (tid < len) {
            int o = s_base + excl;
            d_off[lo + tid] = o;
            d_cur[lo + tid] = o;
            d_dinv[lo + tid] = rsqrtf((float)(v + 1));
        }
    }
    gbar();

    // ---- S3: CSR fill + embedding GEMM (fp32 x converted at staging) ----
    for (int i = gt; i < e; i += GSTR) {
        int dd = dst[i];
        int p = atomicAdd(&d_cur[dd], 1);
        d_srcs[p] = src[i];
    }
    {
        const float* Ws[1] = {emb_w}; const float* Bs[1] = {emb_b};
        void* Os[1] = {(void*)d_h0h}; int ost[1] = {64}; unsigned fl[1] = {1u | 2u | 4u};
        gemm_multi<128, 1, 1>(x, Ws, Ws, Bs, Os, ost, fl, n, sWh, sXh);
    }
    gbar();

    // ---- S5: GCN1 (aggregate h0 in staging) GEMM 64->128, relu, pre-scale ----
    {
        const float* Ws[2] = {c1_w, c1_w + 64 * 64};
        const float* Bs[2] = {c1_b, c1_b + 64};
        void* Os[2] = {(void*)d_l1h, (void*)(d_l1h + 64)};
        int ost[2] = {128, 128}; unsigned fl[2] = {7u, 7u};
        gemm_multi<64, 2, 2>(d_h0h, Ws, Ws, Bs, Os, ost, fl, n, sWh, sXh);
    }
    gbar();

    // ---- S7: GCN2 (aggregate l1 in staging) GEMM 128->128, relu ----
    {
        const float* Ws[2] = {c2_w, c2_w + 64 * 128};
        const float* Bs[2] = {c2_b, c2_b + 64};
        void* Os[2] = {(void*)d_l2h, (void*)(d_l2h + 64)};
        int ost[2] = {128, 128}; unsigned fl[2] = {1u | 4u, 1u | 4u};
        gemm_multi<128, 2, 2>(d_l1h, Ws, Ws, Bs, Os, ost, fl, n, sWh, sXh);
    }
    gbar();

    // ---- S8: tail projections (X = l2 staged once; g, t1h, t1e all fp16) ----
    {
        const float* Ws[3] = {bw1, hw1, ew1};
        const float* Bs[3] = {bb1, hb1, eb1};
        void* Os[3] = {(void*)d_gh, (void*)d_t12h, (void*)(d_t12h + 64)};
        int ost[3] = {64, 128, 128}; unsigned fl[3] = {4u, 5u, 5u};
        gemm_multi<128, 0, 3>(d_l2h, Ws, Ws, Bs, Os, ost, fl, n, sWh, sXh);
    }
    gbar();

    // ---- S9: tm layer-2 GEMM (block-diag) + bond energy ----
    {
        const float* Ws[1] = {hw2}; const float* W2s[1] = {ew2};
        const float* Bs[1] = {(const float*)d_b2c};
        void* Os[1] = {(void*)d_t2x}; int ost[1] = {64}; unsigned fl[1] = {1u | 4u | 8u};
        gemm_multi<128, 0, 1>(d_t12h, Ws, W2s, Bs, Os, ost, fl, n, sWh, sXh);
    }
    {
        int sub = tid & 7;
        float wreg[8];
        #pragma unroll
        for (int j = 0; j < 8; j++) wreg[j] = bw2[sub * 8 + j];
        float b2v = bb2[0];
        const int GROUPS = NB * (NT / 8);
        int g0 = (bid * NT + tid) >> 3;
        float accq = 0.f;
        int cnt = 0;
        for (int eid = g0; eid < e; eid += GROUPS) {
            int s = src[eid], d = dst[eid];
            uint4 us = *(const uint4*)(d_gh + (size_t)s * 64 + sub * 8);
            uint4 ud = *(const uint4*)(d_gh + (size_t)d * 64 + sub * 8);
            float2 s0 = h22f2(us.x), s1 = h22f2(us.y), s2 = h22f2(us.z), s3 = h22f2(us.w);
            float2 t0 = h22f2(ud.x), t1 = h22f2(ud.y), t2 = h22f2(ud.z), t3 = h22f2(ud.w);
            float p = 0.f;
            p += fmaxf(0.5f * (s0.x + t0.x), 0.f) * wreg[0];
            p += fmaxf(0.5f * (s0.y + t0.y), 0.f) * wreg[1];
            p += fmaxf(0.5f * (s1.x + t1.x), 0.f) * wreg[2];
            p += fmaxf(0.5f * (s1.y + t1.y), 0.f) * wreg[3];
            p += fmaxf(0.5f * (s2.x + t2.x), 0.f) * wreg[4];
            p += fmaxf(0.5f * (s2.y + t2.y), 0.f) * wreg[5];
            p += fmaxf(0.5f * (s3.x + t3.x), 0.f) * wreg[6];
            p += fmaxf(0.5f * (s3.y + t3.y), 0.f) * wreg[7];
            p += __shfl_down_sync(0xffffffffu, p, 4, 8);
            p += __shfl_down_sync(0xffffffffu, p, 2, 8);
            p += __shfl_down_sync(0xffffffffu, p, 1, 8);
            if (sub == 0) {
                float dx = pos[d * 3 + 0] - pos[s * 3 + 0];
                float dy = pos[d * 3 + 1] - pos[s * 3 + 1];
                float dz = pos[d * 3 + 2] - pos[s * 3 + 2];
                float L = sqrtf(dx * dx + dy * dy + dz * dz);
                float t = L - 1.5f;
                accq += p + 1000.f * t * t;
                cnt++;
            }
        }
        float vv = accq + b2v * (float)cnt;
        vv += __shfl_down_sync(0xffffffffu, vv, 16);
        vv += __shfl_down_sync(0xffffffffu, vv, 8);
        __syncthreads();
        if (lane == 0) s_red[wid] = vv;
        __syncthreads();
        if (tid < 32) {
            float s = s_red[tid];
            #pragma unroll
            for (int st = 16; st > 0; st >>= 1) s += __shfl_down_sync(0xffffffffu, s, st);
            if (tid == 0) d_pb[bid] = (double)s;
        }
    }
    gbar();

    // ---- S10: tm final dots + sigmoid + mean partials (warp per node) ----
    {
        if (tid < 64) s3w[tid] = (tid < 32) ? hw3[tid] : ew3[tid - 32];
        __syncthreads();
        float b3hv = hb3[0], b3ev = eb3[0];
        float accv = 0.f;
        int part = lane >> 4, li = lane & 15;
        for (int node = bid * 32 + wid; node < n; node += NB * 32) {
            unsigned u = *(const unsigned*)(d_t2x + (size_t)node * 64 + part * 32 + li * 2);
            float2 fv = h22f2(u);
            float p = fv.x * s3w[part * 32 + li * 2] + fv.y * s3w[part * 32 + li * 2 + 1];
            p += __shfl_down_sync(0xffffffffu, p, 8, 16);
            p += __shfl_down_sync(0xffffffffu, p, 4, 16);
            p += __shfl_down_sync(0xffffffffu, p, 2, 16);
            p += __shfl_down_sync(0xffffffffu, p, 1, 16);
            float pe = __shfl_sync(0xffffffffu, p, 16);
            if (lane == 0)
                accv += 0.5f * (1.f / (1.f + expf(-(p + b3hv))) + 1.f / (1.f + expf(-(pe + b3ev))));
        }
        if (lane == 0) s_red[wid] = accv;
        __syncthreads();
        if (tid < 32) {
            float s = s_red[tid];
            #pragma unroll
            for (int st = 16; st > 0; st >>= 1) s += __shfl_down_sync(0xffffffffu, s, st);
            if (tid == 0) d_pt[bid] = (double)s;
        }
    }
    gbar();

    // ---- S11: final scalars (block 0) ----
    if (bid == 0) {
        double* db = (double*)smem_buf;
        if (tid < NB) { db[tid] = d_pb[tid]; db[NB + tid] = d_pt[tid]; }
        __syncthreads();
        if (tid == 0) {
            double eb = 0.0, tm = 0.0;
            for (int i = 0; i < NB; i++) { eb += db[i]; tm += db[NB + i]; }
            tm /= (double)n;
            double et = eb + 3.0;
            if (tm < 0.5) et += (1.0 - tm) * 10.0;
            out[0] = (float)eb;
            out[1] = 1.0f; out[2] = 1.0f; out[3] = 1.0f;
            out[4] = (float)et;
            out[5] = (float)tm;
        }
    }
}

// ---------------- host launcher: ONE kernel launch ----------------
extern "C" void kernel_launch(void* const* d_in, const int* in_sizes, int n_in,
                              void* d_out, int out_size) {
    const float* x     = (const float*)d_in[0];
    const int*   ei    = (const int*)  d_in[1];
    const float* pos   = (const float*)d_in[2];
    /* d_in[3] = batch (unused) */
    const float* emb_w = (const float*)d_in[4];
    const float* emb_b = (const float*)d_in[5];
    const float* c1_w  = (const float*)d_in[6];
    const float* c1_b  = (const float*)d_in[7];
    const float* c2_w  = (const float*)d_in[8];
    const float* c2_b  = (const float*)d_in[9];
    const float* bw1   = (const float*)d_in[10];
    const float* bb1   = (const float*)d_in[11];
    const float* bw2   = (const float*)d_in[12];
    const float* bb2   = (const float*)d_in[13];
    const float* hw1   = (const float*)d_in[14];
    const float* hb1   = (const float*)d_in[15];
    const float* hw2   = (const float*)d_in[16];
    const float* hb2   = (const float*)d_in[17];
    const float* hw3   = (const float*)d_in[18];
    const float* hb3   = (const float*)d_in[19];
    const float* ew1   = (const float*)d_in[20];
    const float* eb1   = (const float*)d_in[21];
    const float* ew2   = (const float*)d_in[22];
    const float* eb2   = (const float*)d_in[23];
    const float* ew3   = (const float*)d_in[24];
    const float* eb3   = (const float*)d_in[25];

    int n = in_sizes[0] / 128;
    int e = in_sizes[1] / 2;
    const int* src = ei;
    const int* dst = ei + e;
    float* out = (float*)d_out;

    const int SMEM = 52224 + 32768;   // 3x sW fp16 [64][136] + sX fp16 [128][128] = 84,992 B
    cudaFuncSetAttribute((const void*)mega, cudaFuncAttributeMaxDynamicSharedMemorySize, SMEM);

    mega<<<NB, NT, SMEM>>>(x, src, dst, pos,
                           emb_w, emb_b, c1_w, c1_b, c2_w, c2_b,
                           bw1, bb1, bw2, bb2,
                           hw1, hb1, hw2, hb2, hw3, hb3,
                           ew1, eb1, ew2, eb2, ew3, eb3,
                           out, n, e);
}

// round 14
// speedup vs baseline: 1.0484x; 1.0484x over previous
#include <cuda_runtime.h>
#include <cuda_fp16.h>
#include <math.h>

#define NB 148
#define NT 1024
#define NMAX 50000
#define EMAX 1600000

typedef unsigned long long u64;

// ---------------- scratch (device globals) ----------------
__device__ __half d_h0h[(size_t)NMAX * 64];   // emb out (pre-scaled by dinv), fp16
__device__ __half d_a0h[(size_t)NMAX * 64];   // aggregated 64, fp16
__device__ __half d_l1h[(size_t)NMAX * 128];  // c1 out (pre-scaled), fp16
__device__ __half d_agh[(size_t)NMAX * 128];  // aggregated 128, fp16
__device__ __half d_l2h[(size_t)NMAX * 128];  // c2 out = final features, fp16
__device__ __half d_gh [(size_t)NMAX * 64];   // bond projection, fp16
__device__ __half d_t12h[(size_t)NMAX * 128]; // [t1h | t1e] fp16
__device__ __half d_t2x[(size_t)NMAX * 64];   // [t2h | t2e] fp16
__device__ float  d_b2c[64];                  // [hb2 | eb2]
__device__ float  d_dinv[NMAX];
__device__ int    d_deg[NMAX];                // ZERO invariant at kernel entry (re-zeroed each call)
__device__ int    d_off[NMAX + 1];
__device__ int    d_cur[NMAX];
__device__ int    d_srcs[EMAX];
__device__ int    d_bsum[NB];
__device__ double d_pb[NB];
__device__ double d_pt[NB];
__device__ unsigned int g_bar;               // monotonic across replays

// ---------------- grid barrier ----------------
__device__ __forceinline__ void gbar() {
    __syncthreads();
    if (threadIdx.x == 0) {
        __threadfence();
        unsigned int old = atomicAdd(&g_bar, 1u);
        unsigned int target = (old / NB + 1u) * NB;
        while (*((volatile unsigned int*)&g_bar) < target) { }
        __threadfence();
    }
    __syncthreads();
}

__device__ __forceinline__ float2 h22f2(unsigned u) {
    __half2 h = *reinterpret_cast<__half2*>(&u);
    return __half22float2(h);
}

__device__ __forceinline__ unsigned smem_u32(const void* p) {
    return (unsigned)__cvta_generic_to_shared(p);
}

__device__ __forceinline__ void mma16816(float* d,
                                         unsigned a0, unsigned a1, unsigned a2, unsigned a3,
                                         unsigned b0, unsigned b1) {
    asm volatile(
        "mma.sync.aligned.m16n8k16.row.col.f32.f16.f16.f32 "
        "{%0,%1,%2,%3}, {%4,%5,%6,%7}, {%8,%9}, {%0,%1,%2,%3};"
        : "+f"(d[0]), "+f"(d[1]), "+f"(d[2]), "+f"(d[3])
        : "r"(a0), "r"(a1), "r"(a2), "r"(a3), "r"(b0), "r"(b1));
}

// ---------------- tensor-core multi-output GEMM ----------------
// All NS weight sets staged ONCE per pass (before tile loop); X staged once per tile.
// CVT: convert fp32 input rows; else copy fp16 rows.
// flags: 1=relu, 2=scale(dinv), 4=fp16 out, 8=block-diag W (Ws upper-left 32x64, Ws2 lower-right)
template <int K, bool CVT, int NS>
__device__ __forceinline__ void gemm_multi(
    const void* xin,
    const float* const* Ws, const float* const* Ws2, const float* const* Bs,
    void* const* Os, const int* osts, const unsigned* flg,
    int n, __half* sWh, __half* sXh) {

    const int C = K / 8;          // 16B chunks per X row
    const int KP = K + 8;         // padded W row (halves)
    const int WSZ = 64 * KP;      // halves per weight spec
    int tid = threadIdx.x;
    int w = tid >> 5, lane = tid & 31;
    int node0 = (w & 7) * 16;     // 8 node groups x 16
    int o0 = (w >> 3) * 16;       // 4 out groups x 16
    int g = lane >> 2, t = lane & 3;
    int ntiles = (n + 127) >> 7;
    unsigned sx_base = smem_u32(sXh);

    // ---- stage ALL weight specs once ----
    #pragma unroll
    for (int s = 0; s < NS; s++) {
        __half* sw = sWh + s * WSZ;
        if (flg[s] & 8u) {
            const float* Wh = Ws[s];
            const float* We = Ws2[s];
            for (int idx = tid; idx < 64 * (KP / 2); idx += NT) {
                int o = idx / (KP / 2), w2 = idx - o * (KP / 2);
                unsigned val = 0u;
                if (o < 32) {
                    if (w2 < 32) {
                        float2 v = *(const float2*)(Wh + o * 64 + w2 * 2);
                        __half2 h = __floats2half2_rn(v.x, v.y);
                        val = *reinterpret_cast<unsigned*>(&h);
                    }
                } else {
                    if (w2 >= 32 && w2 < 64) {
                        float2 v = *(const float2*)(We + (o - 32) * 64 + (w2 - 32) * 2);
                        __half2 h = __floats2half2_rn(v.x, v.y);
                        val = *reinterpret_cast<unsigned*>(&h);
                    }
                }
                *(unsigned*)(sw + o * KP + w2 * 2) = val;
            }
        } else {
            const float* Wp = Ws[s];
            for (int idx = tid; idx < 64 * (K / 2); idx += NT) {
                int o = idx / (K / 2), k2 = idx - o * (K / 2);
                float2 wv = *(const float2*)(Wp + o * K + k2 * 2);
                __half2 h = __floats2half2_rn(wv.x, wv.y);
                *(unsigned*)(sw + o * KP + k2 * 2) = *reinterpret_cast<unsigned*>(&h);
            }
        }
    }
    __syncthreads();

    for (int tile = blockIdx.x; tile < ntiles; tile += NB) {
        int base = tile << 7;
        int nn_max = n - base; if (nn_max > 128) nn_max = 128;
        __syncthreads();                              // prior tile's sX readers done
        // ---- stage X ----
        if (CVT) {
            const float* xf = (const float*)xin;
            for (int idx = tid; idx < 128 * C; idx += NT) {
                int nn = idx / C, c = idx - nn * C;
                uint4 q;
                if (nn < nn_max) {
                    const float* p = xf + (size_t)(base + nn) * K + c * 8;
                    float4 v0 = *(const float4*)p;
                    float4 v1 = *(const float4*)(p + 4);
                    __half2 h0 = __floats2half2_rn(v0.x, v0.y);
                    __half2 h1 = __floats2half2_rn(v0.z, v0.w);
                    __half2 h2 = __floats2half2_rn(v1.x, v1.y);
                    __half2 h3 = __floats2half2_rn(v1.z, v1.w);
                    q.x = *reinterpret_cast<unsigned*>(&h0);
                    q.y = *reinterpret_cast<unsigned*>(&h1);
                    q.z = *reinterpret_cast<unsigned*>(&h2);
                    q.w = *reinterpret_cast<unsigned*>(&h3);
                } else { q = make_uint4(0, 0, 0, 0); }
                *(uint4*)(sXh + nn * K + ((c ^ (nn & 7)) << 3)) = q;
            }
        } else {
            const __half* xh = (const __half*)xin;
            for (int idx = tid; idx < 128 * C; idx += NT) {
                int nn = idx / C, c = idx - nn * C;
                uint4 q = (nn < nn_max)
                    ? *(const uint4*)(xh + (size_t)(base + nn) * K + c * 8)
                    : make_uint4(0, 0, 0, 0);
                *(uint4*)(sXh + nn * K + ((c ^ (nn & 7)) << 3)) = q;
            }
        }
        __syncthreads();

        // ---- compute all specs on the staged tile ----
        #pragma unroll
        for (int s = 0; s < NS; s++) {
            const __half* sw = sWh + s * WSZ;
            unsigned f = flg[s];
            const float* Bp = Bs[s];
            float ba0 = Bp[o0 + t * 2],     ba1 = Bp[o0 + t * 2 + 1];
            float bb0 = Bp[o0 + 8 + t * 2], bb1 = Bp[o0 + 8 + t * 2 + 1];
            float d0[4] = {ba0, ba1, ba0, ba1};
            float d1[4] = {bb0, bb1, bb0, bb1};

            int row = node0 + (lane & 15);
            #pragma unroll
            for (int ks = 0; ks < K / 16; ks++) {
                int chunk = ks * 2 + (lane >> 4);
                unsigned addr = sx_base + (unsigned)(row * (K * 2) + ((chunk ^ (row & 7)) << 4));
                unsigned a0, a1, a2, a3;
                asm volatile("ldmatrix.sync.aligned.m8n8.x4.shared.b16 {%0,%1,%2,%3}, [%4];"
                             : "=r"(a0), "=r"(a1), "=r"(a2), "=r"(a3) : "r"(addr));
                const __half* wb = sw + ks * 16 + t * 2;
                unsigned b00 = *(const unsigned*)(wb + (o0 + g) * KP);
                unsigned b01 = *(const unsigned*)(wb + (o0 + g) * KP + 8);
                unsigned b10 = *(const unsigned*)(wb + (o0 + 8 + g) * KP);
                unsigned b11 = *(const unsigned*)(wb + (o0 + 8 + g) * KP + 8);
                mma16816(d0, a0, a1, a2, a3, b00, b01);
                mma16816(d1, a0, a1, a2, a3, b10, b11);
            }

            int ost = osts[s];
            int nl0 = node0 + g, nl1 = nl0 + 8;
            #pragma unroll
            for (int half_ = 0; half_ < 2; half_++) {
                int nl = half_ ? nl1 : nl0;
                if (nl < nn_max) {
                    int node = base + nl;
                    float v0 = half_ ? d0[2] : d0[0];
                    float v1 = half_ ? d0[3] : d0[1];
                    float v2 = half_ ? d1[2] : d1[0];
                    float v3 = half_ ? d1[3] : d1[1];
                    if (f & 1u) {
                        v0 = fmaxf(v0, 0.f); v1 = fmaxf(v1, 0.f);
                        v2 = fmaxf(v2, 0.f); v3 = fmaxf(v3, 0.f);
                    }
                    if (f & 2u) {
                        float sc = d_dinv[node];
                        v0 *= sc; v1 *= sc; v2 *= sc; v3 *= sc;
                    }
                    if (f & 4u) {
                        __half* op = (__half*)Os[s] + (size_t)node * ost;
                        __half2 h0 = __floats2half2_rn(v0, v1);
                        __half2 h1 = __floats2half2_rn(v2, v3);
                        *(unsigned*)(op + o0 + t * 2)     = *reinterpret_cast<unsigned*>(&h0);
                        *(unsigned*)(op + o0 + 8 + t * 2) = *reinterpret_cast<unsigned*>(&h1);
                    } else {
                        float* op = (float*)Os[s] + (size_t)node * ost;
                        *(float2*)(op + o0 + t * 2)     = make_float2(v0, v1);
                        *(float2*)(op + o0 + 8 + t * 2) = make_float2(v2, v3);
                    }
                }
            }
        }
    }
}

// ---------------- GCN aggregation (fp16 in/out), deg-loop unrolled x8 ----------------
template <int D>
__device__ void agg_stage(const __half* __restrict__ hs, __half* __restrict__ out, int n) {
    const int LPN = D / 4, NPW = 32 / LPN;
    int lane = threadIdx.x & 31;
    int gw = (blockIdx.x * NT + threadIdx.x) >> 5;
    const int TOTW = NB * (NT / 32);
    int sub = lane / LPN;
    int c = (lane % LPN) * 4;
    for (int b = gw; b * NPW < n; b += TOTW) {
        int node = b * NPW + sub;
        if (node < n) {
            uint2 us = *(const uint2*)(hs + (size_t)node * D + c);
            float2 f0 = h22f2(us.x), f1 = h22f2(us.y);
            float4 acc = make_float4(f0.x, f0.y, f1.x, f1.y);
            int j0 = d_off[node], j1 = d_off[node + 1];
            int j = j0;
            for (; j + 7 < j1; j += 8) {
                uint2 u[8];
                #pragma unroll
                for (int q = 0; q < 8; q++)
                    u[q] = *(const uint2*)(hs + (size_t)d_srcs[j + q] * D + c);
                #pragma unroll
                for (int q = 0; q < 8; q++) {
                    float2 a0 = h22f2(u[q].x), a1 = h22f2(u[q].y);
                    acc.x += a0.x; acc.y += a0.y; acc.z += a1.x; acc.w += a1.y;
                }
            }
            for (; j + 3 < j1; j += 4) {
                uint2 u[4];
                #pragma unroll
                for (int q = 0; q < 4; q++)
                    u[q] = *(const uint2*)(hs + (size_t)d_srcs[j + q] * D + c);
                #pragma unroll
                for (int q = 0; q < 4; q++) {
                    float2 a0 = h22f2(u[q].x), a1 = h22f2(u[q].y);
                    acc.x += a0.x; acc.y += a0.y; acc.z += a1.x; acc.w += a1.y;
                }
            }
            for (; j < j1; j++) {
                uint2 u0 = *(const uint2*)(hs + (size_t)d_srcs[j] * D + c);
                float2 a0 = h22f2(u0.x), a1 = h22f2(u0.y);
                acc.x += a0.x; acc.y += a0.y; acc.z += a1.x; acc.w += a1.y;
            }
            float dv = d_dinv[node];
            __half2 o0 = __floats2half2_rn(acc.x * dv, acc.y * dv);
            __half2 o1 = __floats2half2_rn(acc.z * dv, acc.w * dv);
            uint2 u;
            u.x = *reinterpret_cast<unsigned*>(&o0);
            u.y = *reinterpret_cast<unsigned*>(&o1);
            *(uint2*)(out + (size_t)node * D + c) = u;
        }
    }
}

// ---------------- the megakernel ----------------
extern __shared__ float smem_buf[];

__global__ __launch_bounds__(NT, 1) void mega(
    const float* __restrict__ x, const int* __restrict__ src, const int* __restrict__ dst,
    const float* __restrict__ pos,
    const float* __restrict__ emb_w, const float* __restrict__ emb_b,
    const float* __restrict__ c1_w, const float* __restrict__ c1_b,
    const float* __restrict__ c2_w, const float* __restrict__ c2_b,
    const float* __restrict__ bw1, const float* __restrict__ bb1,
    const float* __restrict__ bw2, const float* __restrict__ bb2,
    const float* __restrict__ hw1, const float* __restrict__ hb1,
    const float* __restrict__ hw2, const float* __restrict__ hb2,
    const float* __restrict__ hw3, const float* __restrict__ hb3,
    const float* __restrict__ ew1, const float* __restrict__ eb1,
    const float* __restrict__ ew2, const float* __restrict__ eb2,
    const float* __restrict__ ew3, const float* __restrict__ eb3,
    float* __restrict__ out, int n, int e) {

    __shared__ float s_red[32];
    __shared__ int   s_ired[32];
    __shared__ int   s_all[NB];
    __shared__ int   s_base;
    __shared__ float s3w[64];

    int tid = threadIdx.x, bid = blockIdx.x;
    int lane = tid & 31, wid = tid >> 5;
    int gt = bid * NT + tid;
    const int GSTR = NB * NT;
    __half* sWh = (__half*)smem_buf;                    // up to 3 specs x [64][K+8]
    __half* sXh = (__half*)((char*)smem_buf + 52224);   // [128][K] fp16 swizzled

    // ---- S1: count in-degrees (d_deg is zero at entry — invariant) + b2c build ----
    for (int i = gt; i < e; i += GSTR) atomicAdd(&d_deg[dst[i]], 1);
    if (bid == 0 && tid < 64) d_b2c[tid] = (tid < 32) ? hb2[tid] : eb2[tid - 32];
    gbar();

    // ---- S2a: per-block chunk sums ----
    int chunk = (n + NB - 1) / NB;
    int lo = bid * chunk;
    int len = n - lo; if (len < 0) len = 0; if (len > chunk) len = chunk;
    int v = (tid < len) ? d_deg[lo + tid] : 0;
    {
        int wv = v;
        #pragma unroll
        for (int st = 16; st > 0; st >>= 1) wv += __shfl_down_sync(0xffffffffu, wv, st);
        if (lane == 0) s_ired[wid] = wv;
        __syncthreads();
        if (tid < 32) {
            int s = s_ired[tid];
            #pragma unroll
            for (int st = 16; st > 0; st >>= 1) s += __shfl_down_sync(0xffffffffu, s, st);
            if (tid == 0) d_bsum[bid] = s;
        }
    }
    gbar();

    // ---- S2c: base + local exclusive scan -> off/cur/dinv ----
    if (tid < NB) s_all[tid] = d_bsum[tid];
    __syncthreads();
    if (tid == 0) {
        int b = 0;
        for (int j = 0; j < bid; j++) b += s_all[j];
        s_base = b;
        if (bid == NB - 1) d_off[n] = b + s_all[NB - 1];
    }
    {
        int* a = (int*)smem_buf;
        a[tid] = v;
        __syncthreads();
        for (int st = 1; st < NT; st <<= 1) {
            int t = (tid >= st) ? a[tid - st] : 0;
            __syncthreads();
            a[tid] += t;
            __syncthreads();
        }
        int excl = a[tid] - v;
        if (tid < len) {
            int o = s_base + excl;
            d_off[lo + tid] = o;
            d_cur[lo + tid] = o;
            d_dinv[lo + tid] = rsqrtf((float)(v + 1));
        }
    }
    gbar();

    // ---- S3: CSR fill + re-zero deg (dead after S2c; restores entry invariant) + emb GEMM ----
    for (int i = gt; i < e; i += GSTR) {
        int dd = dst[i];
        int p = atomicAdd(&d_cur[dd], 1);
        d_srcs[p] = src[i];
    }
    for (int i = gt; i < n; i += GSTR) d_deg[i] = 0;
    {
        const float* Ws[1] = {emb_w}; const float* Bs[1] = {emb_b};
        void* Os[1] = {(void*)d_h0h}; int ost[1] = {64}; unsigned fl[1] = {1u | 2u | 4u};
        gemm_multi<128, true, 1>(x, Ws, Ws, Bs, Os, ost, fl, n, sWh, sXh);
    }
    gbar();

    // ---- S4: aggregate 64 ----
    agg_stage<64>(d_h0h, d_a0h, n);
    gbar();

    // ---- S5: GCN1 GEMM (64->128, relu, pre-scale) ----
    {
        const float* Ws[2] = {c1_w, c1_w + 64 * 64};
        const float* Bs[2] = {c1_b, c1_b + 64};
        void* Os[2] = {(void*)d_l1h, (void*)(d_l1h + 64)};
        int ost[2] = {128, 128}; unsigned fl[2] = {7u, 7u};
        gemm_multi<64, false, 2>(d_a0h, Ws, Ws, Bs, Os, ost, fl, n, sWh, sXh);
    }
    gbar();

    // ---- S6: aggregate 128 ----
    agg_stage<128>(d_l1h, d_agh, n);
    gbar();

    // ---- S7: GCN2 GEMM (128->128, relu) ----
    {
        const float* Ws[2] = {c2_w, c2_w + 64 * 128};
        const float* Bs[2] = {c2_b, c2_b + 64};
        void* Os[2] = {(void*)d_l2h, (void*)(d_l2h + 64)};
        int ost[2] = {128, 128}; unsigned fl[2] = {1u | 4u, 1u | 4u};
        gemm_multi<128, false, 2>(d_agh, Ws, Ws, Bs, Os, ost, fl, n, sWh, sXh);
    }
    gbar();

    // ---- S8: tail projections (X = l2 staged once; g, t1h, t1e all fp16) ----
    {
        const float* Ws[3] = {bw1, hw1, ew1};
        const float* Bs[3] = {bb1, hb1, eb1};
        void* Os[3] = {(void*)d_gh, (void*)d_t12h, (void*)(d_t12h + 64)};
        int ost[3] = {64, 128, 128}; unsigned fl[3] = {4u, 5u, 5u};
        gemm_multi<128, false, 3>(d_l2h, Ws, Ws, Bs, Os, ost, fl, n, sWh, sXh);
    }
    gbar();

    // ---- S9: tm layer-2 GEMM (block-diag) + bond energy ----
    {
        const float* Ws[1] = {hw2}; const float* W2s[1] = {ew2};
        const float* Bs[1] = {(const float*)d_b2c};
        void* Os[1] = {(void*)d_t2x}; int ost[1] = {64}; unsigned fl[1] = {1u | 4u | 8u};
        gemm_multi<128, false, 1>(d_t12h, Ws, W2s, Bs, Os, ost, fl, n, sWh, sXh);
    }
    {
        int sub = tid & 7;
        float wreg[8];
        #pragma unroll
        for (int j = 0; j < 8; j++) wreg[j] = bw2[sub * 8 + j];
        float b2v = bb2[0];
        const int GROUPS = NB * (NT / 8);
        int g0 = (bid * NT + tid) >> 3;
        float accq = 0.f;
        int cnt = 0;
        for (int eid = g0; eid < e; eid += GROUPS) {
            int s = src[eid], d = dst[eid];
            uint4 us = *(const uint4*)(d_gh + (size_t)s * 64 + sub * 8);
            uint4 ud = *(const uint4*)(d_gh + (size_t)d * 64 + sub * 8);
            float2 s0 = h22f2(us.x), s1 = h22f2(us.y), s2 = h22f2(us.z), s3 = h22f2(us.w);
            float2 t0 = h22f2(ud.x), t1 = h22f2(ud.y), t2 = h22f2(ud.z), t3 = h22f2(ud.w);
            float p = 0.f;
            p += fmaxf(0.5f * (s0.x + t0.x), 0.f) * wreg[0];
            p += fmaxf(0.5f * (s0.y + t0.y), 0.f) * wreg[1];
            p += fmaxf(0.5f * (s1.x + t1.x), 0.f) * wreg[2];
            p += fmaxf(0.5f * (s1.y + t1.y), 0.f) * wreg[3];
            p += fmaxf(0.5f * (s2.x + t2.x), 0.f) * wreg[4];
            p += fmaxf(0.5f * (s2.y + t2.y), 0.f) * wreg[5];
            p += fmaxf(0.5f * (s3.x + t3.x), 0.f) * wreg[6];
            p += fmaxf(0.5f * (s3.y + t3.y), 0.f) * wreg[7];
            p += __shfl_down_sync(0xffffffffu, p, 4, 8);
            p += __shfl_down_sync(0xffffffffu, p, 2, 8);
            p += __shfl_down_sync(0xffffffffu, p, 1, 8);
            if (sub == 0) {
                float dx = pos[d * 3 + 0] - pos[s * 3 + 0];
                float dy = pos[d * 3 + 1] - pos[s * 3 + 1];
                float dz = pos[d * 3 + 2] - pos[s * 3 + 2];
                float L = sqrtf(dx * dx + dy * dy + dz * dz);
                float t = L - 1.5f;
                accq += p + 1000.f * t * t;
                cnt++;
            }
        }
        float vv = accq + b2v * (float)cnt;
        vv += __shfl_down_sync(0xffffffffu, vv, 16);
        vv += __shfl_down_sync(0xffffffffu, vv, 8);
        __syncthreads();
        if (lane == 0) s_red[wid] = vv;
        __syncthreads();
        if (tid < 32) {
            float s = s_red[tid];
            #pragma unroll
            for (int st = 16; st > 0; st >>= 1) s += __shfl_down_sync(0xffffffffu, s, st);
            if (tid == 0) d_pb[bid] = (double)s;
        }
    }
    gbar();

    // ---- S10: tm final dots + sigmoid + mean partials (warp per node) ----
    {
        if (tid < 64) s3w[tid] = (tid < 32) ? hw3[tid] : ew3[tid - 32];
        __syncthreads();
        float b3hv = hb3[0], b3ev = eb3[0];
        float accv = 0.f;
        int part = lane >> 4, li = lane & 15;
        for (int node = bid * 32 + wid; node < n; node += NB * 32) {
            unsigned u = *(const unsigned*)(d_t2x + (size_t)node * 64 + part * 32 + li * 2);
            float2 fv = h22f2(u);
            float p = fv.x * s3w[part * 32 + li * 2] + fv.y * s3w[part * 32 + li * 2 + 1];
            p += __shfl_down_sync(0xffffffffu, p, 8, 16);
            p += __shfl_down_sync(0xffffffffu, p, 4, 16);
            p += __shfl_down_sync(0xffffffffu, p, 2, 16);
            p += __shfl_down_sync(0xffffffffu, p, 1, 16);
            float pe = __shfl_sync(0xffffffffu, p, 16);
            if (lane == 0)
                accv += 0.5f * (1.f / (1.f + expf(-(p + b3hv))) + 1.f / (1.f + expf(-(pe + b3ev))));
        }
        if (lane == 0) s_red[wid] = accv;
        __syncthreads();
        if (tid < 32) {
            float s = s_red[tid];
            #pragma unroll
            for (int st = 16; st > 0; st >>= 1) s += __shfl_down_sync(0xffffffffu, s, st);
            if (tid == 0) d_pt[bid] = (double)s;
        }
    }
    gbar();

    // ---- S11: final scalars (block 0) ----
    if (bid == 0) {
        double* db = (double*)smem_buf;
        if (tid < NB) { db[tid] = d_pb[tid]; db[NB + tid] = d_pt[tid]; }
        __syncthreads();
        if (tid == 0) {
            double eb = 0.0, tm = 0.0;
            for (int i = 0; i < NB; i++) { eb += db[i]; tm += db[NB + i]; }
            tm /= (double)n;
            double et = eb + 3.0;
            if (tm < 0.5) et += (1.0 - tm) * 10.0;
            out[0] = (float)eb;
            out[1] = 1.0f; out[2] = 1.0f; out[3] = 1.0f;
            out[4] = (float)et;
            out[5] = (float)tm;
        }
    }
}

// ---------------- host launcher: ONE kernel launch ----------------
extern "C" void kernel_launch(void* const* d_in, const int* in_sizes, int n_in,
                              void* d_out, int out_size) {
    const float* x     = (const float*)d_in[0];
    const int*   ei    = (const int*)  d_in[1];
    const float* pos   = (const float*)d_in[2];
    /* d_in[3] = batch (unused) */
    const float* emb_w = (const float*)d_in[4];
    const float* emb_b = (const float*)d_in[5];
    const float* c1_w  = (const float*)d_in[6];
    const float* c1_b  = (const float*)d_in[7];
    const float* c2_w  = (const float*)d_in[8];
    const float* c2_b  = (const float*)d_in[9];
    const float* bw1   = (const float*)d_in[10];
    const float* bb1   = (const float*)d_in[11];
    const float* bw2   = (const float*)d_in[12];
    const float* bb2   = (const float*)d_in[13];
    const float* hw1   = (const float*)d_in[14];
    const float* hb1   = (const float*)d_in[15];
    const float* hw2   = (const float*)d_in[16];
    const float* hb2   = (const float*)d_in[17];
    const float* hw3   = (const float*)d_in[18];
    const float* hb3   = (const float*)d_in[19];
    const float* ew1   = (const float*)d_in[20];
    const float* eb1   = (const float*)d_in[21];
    const float* ew2   = (const float*)d_in[22];
    const float* eb2   = (const float*)d_in[23];
    const float* ew3   = (const float*)d_in[24];
    const float* eb3   = (const float*)d_in[25];

    int n = in_sizes[0] / 128;
    int e = in_sizes[1] / 2;
    const int* src = ei;
    const int* dst = ei + e;
    float* out = (float*)d_out;

    const int SMEM = 52224 + 32768;   // 3x sW fp16 [64][136] + sX fp16 [128][128] = 84,992 B
    cudaFuncSetAttribute((const void*)mega, cudaFuncAttributeMaxDynamicSharedMemorySize, SMEM);

    mega<<<NB, NT, SMEM>>>(x, src, dst, pos,
                           emb_w, emb_b, c1_w, c1_b, c2_w, c2_b,
                           bw1, bb1, bw2, bb2,
                           hw1, hb1, hw2, hb2, hw3, hb3,
                           ew1, eb1, ew2, eb2, ew3, eb3,
                           out, n, e);
}

// round 15
// speedup vs baseline: 1.0720x; 1.0226x over previous
#include <cuda_runtime.h>
#include <cuda_fp16.h>
#include <math.h>

#define NB 148
#define NT 1024
#define NMAX 50000
#define EMAX 1600000

typedef unsigned long long u64;

// ---------------- scratch (device globals) ----------------
__device__ __half d_h0h[(size_t)NMAX * 64];   // emb out (pre-scaled by dinv), fp16
__device__ __half d_a0h[(size_t)NMAX * 64];   // aggregated 64, fp16
__device__ __half d_l1h[(size_t)NMAX * 128];  // c1 out (pre-scaled), fp16
__device__ __half d_agh[(size_t)NMAX * 128];  // aggregated 128, fp16
__device__ __half d_l2h[(size_t)NMAX * 128];  // c2 out = final features, fp16
__device__ __half d_gh [(size_t)NMAX * 64];   // bond projection, fp16
__device__ __half d_t12h[(size_t)NMAX * 128]; // [t1h | t1e] fp16
__device__ float  d_b2c[64];                  // [hb2 | eb2]
__device__ float  d_dinv[NMAX];
__device__ int    d_deg[NMAX];                // ZERO invariant at kernel entry (re-zeroed each call)
__device__ int    d_off[NMAX + 1];
__device__ int    d_cur[NMAX];
__device__ int    d_srcs[EMAX];
__device__ int    d_bsum[NB];
__device__ double d_pb[NB];
__device__ double d_pt[NB];
__device__ unsigned int g_bar;               // monotonic across replays

// ---------------- grid barrier ----------------
__device__ __forceinline__ void gbar() {
    __syncthreads();
    if (threadIdx.x == 0) {
        __threadfence();
        unsigned int old = atomicAdd(&g_bar, 1u);
        unsigned int target = (old / NB + 1u) * NB;
        while (*((volatile unsigned int*)&g_bar) < target) { }
        __threadfence();
    }
    __syncthreads();
}

__device__ __forceinline__ float2 h22f2(unsigned u) {
    __half2 h = *reinterpret_cast<__half2*>(&u);
    return __half22float2(h);
}

__device__ __forceinline__ unsigned smem_u32(const void* p) {
    return (unsigned)__cvta_generic_to_shared(p);
}

__device__ __forceinline__ void mma16816(float* d,
                                         unsigned a0, unsigned a1, unsigned a2, unsigned a3,
                                         unsigned b0, unsigned b1) {
    asm volatile(
        "mma.sync.aligned.m16n8k16.row.col.f32.f16.f16.f32 "
        "{%0,%1,%2,%3}, {%4,%5,%6,%7}, {%8,%9}, {%0,%1,%2,%3};"
        : "+f"(d[0]), "+f"(d[1]), "+f"(d[2]), "+f"(d[3])
        : "r"(a0), "r"(a1), "r"(a2), "r"(a3), "r"(b0), "r"(b1));
}

// ---------------- tensor-core multi-output GEMM ----------------
// All NS weight sets staged ONCE per pass; X staged once per tile.
// CVT: convert fp32 input rows; else copy fp16 rows.
// TMRED: NS==1; instead of storing D, reduce with w3 (s_w3c) + sigmoid into *tm_acc (tid<128).
// flags: 1=relu, 2=scale(dinv), 4=fp16 out, 8=block-diag W (Ws upper-left 32x64, Ws2 lower-right)
template <int K, bool CVT, int NS, bool TMRED>
__device__ __forceinline__ void gemm_multi(
    const void* xin,
    const float* const* Ws, const float* const* Ws2, const float* const* Bs,
    void* const* Os, const int* osts, const unsigned* flg,
    int n, __half* sWh, __half* sXh,
    float* s_pq, const float* s_w3c, float b3h, float b3e, float* tm_acc) {

    const int C = K / 8;          // 16B chunks per X row
    const int KP = K + 8;         // padded W row (halves)
    const int WSZ = 64 * KP;      // halves per weight spec
    int tid = threadIdx.x;
    int w = tid >> 5, lane = tid & 31;
    int node0 = (w & 7) * 16;     // 8 node groups x 16
    int o0 = (w >> 3) * 16;       // 4 out groups x 16
    int g = lane >> 2, t = lane & 3;
    int ntiles = (n + 127) >> 7;
    unsigned sx_base = smem_u32(sXh);

    // ---- stage ALL weight specs once ----
    #pragma unroll
    for (int s = 0; s < NS; s++) {
        __half* sw = sWh + s * WSZ;
        if (flg[s] & 8u) {
            const float* Wh = Ws[s];
            const float* We = Ws2[s];
            for (int idx = tid; idx < 64 * (KP / 2); idx += NT) {
                int o = idx / (KP / 2), w2 = idx - o * (KP / 2);
                unsigned val = 0u;
                if (o < 32) {
                    if (w2 < 32) {
                        float2 v = *(const float2*)(Wh + o * 64 + w2 * 2);
                        __half2 h = __floats2half2_rn(v.x, v.y);
                        val = *reinterpret_cast<unsigned*>(&h);
                    }
                } else {
                    if (w2 >= 32 && w2 < 64) {
                        float2 v = *(const float2*)(We + (o - 32) * 64 + (w2 - 32) * 2);
                        __half2 h = __floats2half2_rn(v.x, v.y);
                        val = *reinterpret_cast<unsigned*>(&h);
                    }
                }
                *(unsigned*)(sw + o * KP + w2 * 2) = val;
            }
        } else {
            const float* Wp = Ws[s];
            for (int idx = tid; idx < 64 * (K / 2); idx += NT) {
                int o = idx / (K / 2), k2 = idx - o * (K / 2);
                float2 wv = *(const float2*)(Wp + o * K + k2 * 2);
                __half2 h = __floats2half2_rn(wv.x, wv.y);
                *(unsigned*)(sw + o * KP + k2 * 2) = *reinterpret_cast<unsigned*>(&h);
            }
        }
    }
    __syncthreads();

    for (int tile = blockIdx.x; tile < ntiles; tile += NB) {
        int base = tile << 7;
        int nn_max = n - base; if (nn_max > 128) nn_max = 128;
        __syncthreads();                              // prior tile's sX/s_pq readers done
        // ---- stage X (+ zero tm partials) ----
        if (TMRED) {
            if (tid < 256) s_pq[tid] = 0.f;
        }
        if (CVT) {
            const float* xf = (const float*)xin;
            for (int idx = tid; idx < 128 * C; idx += NT) {
                int nn = idx / C, c = idx - nn * C;
                uint4 q;
                if (nn < nn_max) {
                    const float* p = xf + (size_t)(base + nn) * K + c * 8;
                    float4 v0 = *(const float4*)p;
                    float4 v1 = *(const float4*)(p + 4);
                    __half2 h0 = __floats2half2_rn(v0.x, v0.y);
                    __half2 h1 = __floats2half2_rn(v0.z, v0.w);
                    __half2 h2 = __floats2half2_rn(v1.x, v1.y);
                    __half2 h3 = __floats2half2_rn(v1.z, v1.w);
                    q.x = *reinterpret_cast<unsigned*>(&h0);
                    q.y = *reinterpret_cast<unsigned*>(&h1);
                    q.z = *reinterpret_cast<unsigned*>(&h2);
                    q.w = *reinterpret_cast<unsigned*>(&h3);
                } else { q = make_uint4(0, 0, 0, 0); }
                *(uint4*)(sXh + nn * K + ((c ^ (nn & 7)) << 3)) = q;
            }
        } else {
            const __half* xh = (const __half*)xin;
            for (int idx = tid; idx < 128 * C; idx += NT) {
                int nn = idx / C, c = idx - nn * C;
                uint4 q = (nn < nn_max)
                    ? *(const uint4*)(xh + (size_t)(base + nn) * K + c * 8)
                    : make_uint4(0, 0, 0, 0);
                *(uint4*)(sXh + nn * K + ((c ^ (nn & 7)) << 3)) = q;
            }
        }
        __syncthreads();

        // ---- compute all specs on the staged tile ----
        #pragma unroll
        for (int s = 0; s < NS; s++) {
            const __half* sw = sWh + s * WSZ;
            unsigned f = flg[s];
            const float* Bp = Bs[s];
            float ba0 = Bp[o0 + t * 2],     ba1 = Bp[o0 + t * 2 + 1];
            float bb0 = Bp[o0 + 8 + t * 2], bb1 = Bp[o0 + 8 + t * 2 + 1];
            float d0[4] = {ba0, ba1, ba0, ba1};
            float d1[4] = {bb0, bb1, bb0, bb1};

            int row = node0 + (lane & 15);
            #pragma unroll
            for (int ks = 0; ks < K / 16; ks++) {
                int chunk = ks * 2 + (lane >> 4);
                unsigned addr = sx_base + (unsigned)(row * (K * 2) + ((chunk ^ (row & 7)) << 4));
                unsigned a0, a1, a2, a3;
                asm volatile("ldmatrix.sync.aligned.m8n8.x4.shared.b16 {%0,%1,%2,%3}, [%4];"
                             : "=r"(a0), "=r"(a1), "=r"(a2), "=r"(a3) : "r"(addr));
                const __half* wb = sw + ks * 16 + t * 2;
                unsigned b00 = *(const unsigned*)(wb + (o0 + g) * KP);
                unsigned b01 = *(const unsigned*)(wb + (o0 + g) * KP + 8);
                unsigned b10 = *(const unsigned*)(wb + (o0 + 8 + g) * KP);
                unsigned b11 = *(const unsigned*)(wb + (o0 + 8 + g) * KP + 8);
                mma16816(d0, a0, a1, a2, a3, b00, b01);
                mma16816(d1, a0, a1, a2, a3, b10, b11);
            }

            int ost = osts[s];
            int nl0 = node0 + g, nl1 = nl0 + 8;
            #pragma unroll
            for (int half_ = 0; half_ < 2; half_++) {
                int nl = half_ ? nl1 : nl0;
                if (nl < nn_max) {
                    int node = base + nl;
                    float v0 = half_ ? d0[2] : d0[0];
                    float v1 = half_ ? d0[3] : d0[1];
                    float v2 = half_ ? d1[2] : d1[0];
                    float v3 = half_ ? d1[3] : d1[1];
                    if (f & 1u) {
                        v0 = fmaxf(v0, 0.f); v1 = fmaxf(v1, 0.f);
                        v2 = fmaxf(v2, 0.f); v3 = fmaxf(v3, 0.f);
                    }
                    if (f & 2u) {
                        float sc = d_dinv[node];
                        v0 *= sc; v1 *= sc; v2 *= sc; v3 *= sc;
                    }
                    if (TMRED) {
                        // dot with w3 slice; route to h-part (o0<32) or e-part
                        float c = v0 * s_w3c[o0 + t * 2] + v1 * s_w3c[o0 + t * 2 + 1]
                                + v2 * s_w3c[o0 + 8 + t * 2] + v3 * s_w3c[o0 + 8 + t * 2 + 1];
                        atomicAdd(&s_pq[(o0 < 32 ? 0 : 128) + nl], c);
                    } else if (f & 4u) {
                        __half* op = (__half*)Os[s] + (size_t)node * ost;
                        __half2 h0 = __floats2half2_rn(v0, v1);
                        __half2 h1 = __floats2half2_rn(v2, v3);
                        *(unsigned*)(op + o0 + t * 2)     = *reinterpret_cast<unsigned*>(&h0);
                        *(unsigned*)(op + o0 + 8 + t * 2) = *reinterpret_cast<unsigned*>(&h1);
                    } else {
                        float* op = (float*)Os[s] + (size_t)node * ost;
                        *(float2*)(op + o0 + t * 2)     = make_float2(v0, v1);
                        *(float2*)(op + o0 + 8 + t * 2) = make_float2(v2, v3);
                    }
                }
            }
        }

        if (TMRED) {
            __syncthreads();           // all epilogue atomics done
            if (tid < 128 && tid < nn_max) {
                float ph = s_pq[tid], pe = s_pq[128 + tid];
                *tm_acc += 0.5f * (1.f / (1.f + expf(-(ph + b3h)))
                                 + 1.f / (1.f + expf(-(pe + b3e))));
            }
        }
    }
}

// ---------------- GCN aggregation (fp16 in/out), deg-loop unrolled x8 ----------------
template <int D>
__device__ void agg_stage(const __half* __restrict__ hs, __half* __restrict__ out, int n) {
    const int LPN = D / 4, NPW = 32 / LPN;
    int lane = threadIdx.x & 31;
    int gw = (blockIdx.x * NT + threadIdx.x) >> 5;
    const int TOTW = NB * (NT / 32);
    int sub = lane / LPN;
    int c = (lane % LPN) * 4;
    for (int b = gw; b * NPW < n; b += TOTW) {
        int node = b * NPW + sub;
        if (node < n) {
            uint2 us = *(const uint2*)(hs + (size_t)node * D + c);
            float2 f0 = h22f2(us.x), f1 = h22f2(us.y);
            float4 acc = make_float4(f0.x, f0.y, f1.x, f1.y);
            int j0 = d_off[node], j1 = d_off[node + 1];
            int j = j0;
            for (; j + 7 < j1; j += 8) {
                uint2 u[8];
                #pragma unroll
                for (int q = 0; q < 8; q++)
                    u[q] = *(const uint2*)(hs + (size_t)d_srcs[j + q] * D + c);
                #pragma unroll
                for (int q = 0; q < 8; q++) {
                    float2 a0 = h22f2(u[q].x), a1 = h22f2(u[q].y);
                    acc.x += a0.x; acc.y += a0.y; acc.z += a1.x; acc.w += a1.y;
                }
            }
            for (; j + 3 < j1; j += 4) {
                uint2 u[4];
                #pragma unroll
                for (int q = 0; q < 4; q++)
                    u[q] = *(const uint2*)(hs + (size_t)d_srcs[j + q] * D + c);
                #pragma unroll
                for (int q = 0; q < 4; q++) {
                    float2 a0 = h22f2(u[q].x), a1 = h22f2(u[q].y);
                    acc.x += a0.x; acc.y += a0.y; acc.z += a1.x; acc.w += a1.y;
                }
            }
            for (; j < j1; j++) {
                uint2 u0 = *(const uint2*)(hs + (size_t)d_srcs[j] * D + c);
                float2 a0 = h22f2(u0.x), a1 = h22f2(u0.y);
                acc.x += a0.x; acc.y += a0.y; acc.z += a1.x; acc.w += a1.y;
            }
            float dv = d_dinv[node];
            __half2 o0 = __floats2half2_rn(acc.x * dv, acc.y * dv);
            __half2 o1 = __floats2half2_rn(acc.z * dv, acc.w * dv);
            uint2 u;
            u.x = *reinterpret_cast<unsigned*>(&o0);
            u.y = *reinterpret_cast<unsigned*>(&o1);
            *(uint2*)(out + (size_t)node * D + c) = u;
        }
    }
}

// ---------------- the megakernel ----------------
extern __shared__ float smem_buf[];

__global__ __launch_bounds__(NT, 1) void mega(
    const float* __restrict__ x, const int* __restrict__ src, const int* __restrict__ dst,
    const float* __restrict__ pos,
    const float* __restrict__ emb_w, const float* __restrict__ emb_b,
    const float* __restrict__ c1_w, const float* __restrict__ c1_b,
    const float* __restrict__ c2_w, const float* __restrict__ c2_b,
    const float* __restrict__ bw1, const float* __restrict__ bb1,
    const float* __restrict__ bw2, const float* __restrict__ bb2,
    const float* __restrict__ hw1, const float* __restrict__ hb1,
    const float* __restrict__ hw2, const float* __restrict__ hb2,
    const float* __restrict__ hw3, const float* __restrict__ hb3,
    const float* __restrict__ ew1, const float* __restrict__ eb1,
    const float* __restrict__ ew2, const float* __restrict__ eb2,
    const float* __restrict__ ew3, const float* __restrict__ eb3,
    float* __restrict__ out, int n, int e) {

    __shared__ float s_red[32];
    __shared__ int   s_ired[32];
    __shared__ int   s_all[NB];
    __shared__ int   s_base;
    __shared__ float s_w3c[64];
    __shared__ float s_pq[256];

    int tid = threadIdx.x, bid = blockIdx.x;
    int lane = tid & 31, wid = tid >> 5;
    int gt = bid * NT + tid;
    const int GSTR = NB * NT;
    __half* sWh = (__half*)smem_buf;                    // up to 3 specs x [64][K+8]
    __half* sXh = (__half*)((char*)smem_buf + 52224);   // [128][K] fp16 swizzled

    // ---- S1: count in-degrees (d_deg zero at entry) + bias/w3 staging ----
    for (int i = gt; i < e; i += GSTR) atomicAdd(&d_deg[dst[i]], 1);
    if (bid == 0 && tid < 64) d_b2c[tid] = (tid < 32) ? hb2[tid] : eb2[tid - 32];
    gbar();

    // ---- S2a: per-block chunk sums ----
    int chunk = (n + NB - 1) / NB;
    int lo = bid * chunk;
    int len = n - lo; if (len < 0) len = 0; if (len > chunk) len = chunk;
    int v = (tid < len) ? d_deg[lo + tid] : 0;
    {
        int wv = v;
        #pragma unroll
        for (int st = 16; st > 0; st >>= 1) wv += __shfl_down_sync(0xffffffffu, wv, st);
        if (lane == 0) s_ired[wid] = wv;
        __syncthreads();
        if (tid < 32) {
            int s = s_ired[tid];
            #pragma unroll
            for (int st = 16; st > 0; st >>= 1) s += __shfl_down_sync(0xffffffffu, s, st);
            if (tid == 0) d_bsum[bid] = s;
        }
    }
    gbar();

    // ---- S2c: base + local exclusive scan -> off/cur/dinv ----
    if (tid < NB) s_all[tid] = d_bsum[tid];
    __syncthreads();
    if (tid == 0) {
        int b = 0;
        for (int j = 0; j < bid; j++) b += s_all[j];
        s_base = b;
        if (bid == NB - 1) d_off[n] = b + s_all[NB - 1];
    }
    {
        int* a = (int*)smem_buf;
        a[tid] = v;
        __syncthreads();
        for (int st = 1; st < NT; st <<= 1) {
            int t = (tid >= st) ? a[tid - st] : 0;
            __syncthreads();
            a[tid] += t;
            __syncthreads();
        }
        int excl = a[tid] - v;
        if (tid < len) {
            int o = s_base + excl;
            d_off[lo + tid] = o;
            d_cur[lo + tid] = o;
            d_dinv[lo + tid] = rsqrtf((float)(v + 1));
        }
    }
    gbar();

    // ---- S3: CSR fill + re-zero deg (restores entry invariant) + emb GEMM ----
    for (int i = gt; i < e; i += GSTR) {
        int dd = dst[i];
        int p = atomicAdd(&d_cur[dd], 1);
        d_srcs[p] = src[i];
    }
    for (int i = gt; i < n; i += GSTR) d_deg[i] = 0;
    {
        const float* Ws[1] = {emb_w}; const float* Bs[1] = {emb_b};
        void* Os[1] = {(void*)d_h0h}; int ost[1] = {64}; unsigned fl[1] = {1u | 2u | 4u};
        gemm_multi<128, true, 1, false>(x, Ws, Ws, Bs, Os, ost, fl, n, sWh, sXh,
                                        nullptr, nullptr, 0.f, 0.f, nullptr);
    }
    gbar();

    // ---- S4: aggregate 64 ----
    agg_stage<64>(d_h0h, d_a0h, n);
    gbar();

    // ---- S5: GCN1 GEMM (64->128, relu, pre-scale) ----
    {
        const float* Ws[2] = {c1_w, c1_w + 64 * 64};
        const float* Bs[2] = {c1_b, c1_b + 64};
        void* Os[2] = {(void*)d_l1h, (void*)(d_l1h + 64)};
        int ost[2] = {128, 128}; unsigned fl[2] = {7u, 7u};
        gemm_multi<64, false, 2, false>(d_a0h, Ws, Ws, Bs, Os, ost, fl, n, sWh, sXh,
                                        nullptr, nullptr, 0.f, 0.f, nullptr);
    }
    gbar();

    // ---- S6: aggregate 128 ----
    agg_stage<128>(d_l1h, d_agh, n);
    gbar();

    // ---- S7: GCN2 GEMM (128->128, relu) ----
    {
        const float* Ws[2] = {c2_w, c2_w + 64 * 128};
        const float* Bs[2] = {c2_b, c2_b + 64};
        void* Os[2] = {(void*)d_l2h, (void*)(d_l2h + 64)};
        int ost[2] = {128, 128}; unsigned fl[2] = {1u | 4u, 1u | 4u};
        gemm_multi<128, false, 2, false>(d_agh, Ws, Ws, Bs, Os, ost, fl, n, sWh, sXh,
                                         nullptr, nullptr, 0.f, 0.f, nullptr);
    }
    gbar();

    // ---- S8: tail projections (X = l2 staged once; g, t1h, t1e all fp16) ----
    {
        const float* Ws[3] = {bw1, hw1, ew1};
        const float* Bs[3] = {bb1, hb1, eb1};
        void* Os[3] = {(void*)d_gh, (void*)d_t12h, (void*)(d_t12h + 64)};
        int ost[3] = {64, 128, 128}; unsigned fl[3] = {4u, 5u, 5u};
        gemm_multi<128, false, 3, false>(d_l2h, Ws, Ws, Bs, Os, ost, fl, n, sWh, sXh,
                                         nullptr, nullptr, 0.f, 0.f, nullptr);
    }
    gbar();

    // ---- S9: tm layer-2 GEMM (block-diag) with fused w3/sigmoid reduction + bond ----
    {
        if (tid < 64) s_w3c[tid] = (tid < 32) ? hw3[tid] : ew3[tid - 32];
        __syncthreads();
        float tmacc = 0.f;
        const float* Ws[1] = {hw2}; const float* W2s[1] = {ew2};
        const float* Bs[1] = {(const float*)d_b2c};
        void* Os[1] = {nullptr}; int ost[1] = {0}; unsigned fl[1] = {1u | 8u};
        gemm_multi<128, false, 1, true>(d_t12h, Ws, W2s, Bs, Os, ost, fl, n, sWh, sXh,
                                        s_pq, s_w3c, hb3[0], eb3[0], &tmacc);
        // block-reduce tmacc (nonzero only on tid<128)
        __syncthreads();
        float tv = tmacc;
        #pragma unroll
        for (int st = 16; st > 0; st >>= 1) tv += __shfl_down_sync(0xffffffffu, tv, st);
        if (lane == 0) s_red[wid] = tv;
        __syncthreads();
        if (tid < 32) {
            float s = s_red[tid];
            #pragma unroll
            for (int st = 16; st > 0; st >>= 1) s += __shfl_down_sync(0xffffffffu, s, st);
            if (tid == 0) d_pt[bid] = (double)s;
        }
        __syncthreads();
    }
    {
        int sub = tid & 7;
        float wreg[8];
        #pragma unroll
        for (int j = 0; j < 8; j++) wreg[j] = bw2[sub * 8 + j];
        float b2v = bb2[0];
        const int GROUPS = NB * (NT / 8);
        int g0 = (bid * NT + tid) >> 3;
        float accq = 0.f;
        int cnt = 0;
        for (int eid = g0; eid < e; eid += GROUPS) {
            int s = src[eid], d = dst[eid];
            uint4 us = *(const uint4*)(d_gh + (size_t)s * 64 + sub * 8);
            uint4 ud = *(const uint4*)(d_gh + (size_t)d * 64 + sub * 8);
            float2 s0 = h22f2(us.x), s1 = h22f2(us.y), s2 = h22f2(us.z), s3 = h22f2(us.w);
            float2 t0 = h22f2(ud.x), t1 = h22f2(ud.y), t2 = h22f2(ud.z), t3 = h22f2(ud.w);
            float p = 0.f;
            p += fmaxf(0.5f * (s0.x + t0.x), 0.f) * wreg[0];
            p += fmaxf(0.5f * (s0.y + t0.y), 0.f) * wreg[1];
            p += fmaxf(0.5f * (s1.x + t1.x), 0.f) * wreg[2];
            p += fmaxf(0.5f * (s1.y + t1.y), 0.f) * wreg[3];
            p += fmaxf(0.5f * (s2.x + t2.x), 0.f) * wreg[4];
            p += fmaxf(0.5f * (s2.y + t2.y), 0.f) * wreg[5];
            p += fmaxf(0.5f * (s3.x + t3.x), 0.f) * wreg[6];
            p += fmaxf(0.5f * (s3.y + t3.y), 0.f) * wreg[7];
            p += __shfl_down_sync(0xffffffffu, p, 4, 8);
            p += __shfl_down_sync(0xffffffffu, p, 2, 8);
            p += __shfl_down_sync(0xffffffffu, p, 1, 8);
            if (sub == 0) {
                float dx = pos[d * 3 + 0] - pos[s * 3 + 0];
                float dy = pos[d * 3 + 1] - pos[s * 3 + 1];
                float dz = pos[d * 3 + 2] - pos[s * 3 + 2];
                float L = sqrtf(dx * dx + dy * dy + dz * dz);
                float t = L - 1.5f;
                accq += p + 1000.f * t * t;
                cnt++;
            }
        }
        float vv = accq + b2v * (float)cnt;
        vv += __shfl_down_sync(0xffffffffu, vv, 16);
        vv += __shfl_down_sync(0xffffffffu, vv, 8);
        if (lane == 0) s_red[wid] = vv;
        __syncthreads();
        if (tid < 32) {
            float s = s_red[tid];
            #pragma unroll
            for (int st = 16; st > 0; st >>= 1) s += __shfl_down_sync(0xffffffffu, s, st);
            if (tid == 0) d_pb[bid] = (double)s;
        }
    }
    gbar();

    // ---- S11: final scalars (block 0) ----
    if (bid == 0) {
        double* db = (double*)smem_buf;
        if (tid < NB) { db[tid] = d_pb[tid]; db[NB + tid] = d_pt[tid]; }
        __syncthreads();
        if (tid == 0) {
            double eb = 0.0, tm = 0.0;
            for (int i = 0; i < NB; i++) { eb += db[i]; tm += db[NB + i]; }
            tm /= (double)n;
            double et = eb + 3.0;
            if (tm < 0.5) et += (1.0 - tm) * 10.0;
            out[0] = (float)eb;
            out[1] = 1.0f; out[2] = 1.0f; out[3] = 1.0f;
            out[4] = (float)et;
            out[5] = (float)tm;
        }
    }
}

// ---------------- host launcher: ONE kernel launch ----------------
extern "C" void kernel_launch(void* const* d_in, const int* in_sizes, int n_in,
                              void* d_out, int out_size) {
    const float* x     = (const float*)d_in[0];
    const int*   ei    = (const int*)  d_in[1];
    const float* pos   = (const float*)d_in[2];
    /* d_in[3] = batch (unused) */
    const float* emb_w = (const float*)d_in[4];
    const float* emb_b = (const float*)d_in[5];
    const float* c1_w  = (const float*)d_in[6];
    const float* c1_b  = (const float*)d_in[7];
    const float* c2_w  = (const float*)d_in[8];
    const float* c2_b  = (const float*)d_in[9];
    const float* bw1   = (const float*)d_in[10];
    const float* bb1   = (const float*)d_in[11];
    const float* bw2   = (const float*)d_in[12];
    const float* bb2   = (const float*)d_in[13];
    const float* hw1   = (const float*)d_in[14];
    const float* hb1   = (const float*)d_in[15];
    const float* hw2   = (const float*)d_in[16];
    const float* hb2   = (const float*)d_in[17];
    const float* hw3   = (const float*)d_in[18];
    const float* hb3   = (const float*)d_in[19];
    const float* ew1   = (const float*)d_in[20];
    const float* eb1   = (const float*)d_in[21];
    const float* ew2   = (const float*)d_in[22];
    const float* eb2   = (const float*)d_in[23];
    const float* ew3   = (const float*)d_in[24];
    const float* eb3   = (const float*)d_in[25];

    int n = in_sizes[0] / 128;
    int e = in_sizes[1] / 2;
    const int* src = ei;
    const int* dst = ei + e;
    float* out = (float*)d_out;

    const int SMEM = 52224 + 32768;   // 3x sW fp16 [64][136] + sX fp16 [128][128] = 84,992 B
    cudaFuncSetAttribute((const void*)mega, cudaFuncAttributeMaxDynamicSharedMemorySize, SMEM);

    mega<<<NB, NT, SMEM>>>(x, src, dst, pos,
                           emb_w, emb_b, c1_w, c1_b, c2_w, c2_b,
                           bw1, bb1, bw2, bb2,
                           hw1, hb1, hw2, hb2, hw3, hb3,
                           ew1, eb1, ew2, eb2, ew3, eb3,
                           out, n, e);
}

// round 16
// speedup vs baseline: 1.0929x; 1.0195x over previous
#include <cuda_runtime.h>
#include <cuda_fp16.h>
#include <math.h>

#define NB 148
#define NT 1024
#define NMAX 50000
#define EMAX 1600000

typedef unsigned long long u64;

// ---------------- scratch (device globals) ----------------
__device__ __half d_h0h[(size_t)NMAX * 64];   // emb out (pre-scaled by dinv), fp16
__device__ __half d_a0h[(size_t)NMAX * 64];   // aggregated 64, fp16
__device__ __half d_l1h[(size_t)NMAX * 128];  // c1 out (pre-scaled), fp16
__device__ __half d_agh[(size_t)NMAX * 128];  // aggregated 128, fp16
__device__ __half d_l2h[(size_t)NMAX * 128];  // c2 out = final features, fp16
__device__ __half d_gh [(size_t)NMAX * 64];   // bond projection, fp16
__device__ float  d_b2c[64];                  // [hb2 | eb2]
__device__ float  d_dinv[NMAX];
__device__ int    d_deg[NMAX];                // ZERO invariant at kernel entry (re-zeroed each call)
__device__ int    d_off[NMAX + 1];
__device__ int    d_cur[NMAX];
__device__ int    d_srcs[EMAX];
__device__ int    d_bsum[NB];
__device__ double d_pb[NB];
__device__ double d_pt[NB];
__device__ unsigned int g_bar;               // monotonic across replays

// ---------------- grid barrier ----------------
__device__ __forceinline__ void gbar() {
    __syncthreads();
    if (threadIdx.x == 0) {
        __threadfence();
        unsigned int old = atomicAdd(&g_bar, 1u);
        unsigned int target = (old / NB + 1u) * NB;
        while (*((volatile unsigned int*)&g_bar) < target) { }
        __threadfence();
    }
    __syncthreads();
}

__device__ __forceinline__ float2 h22f2(unsigned u) {
    __half2 h = *reinterpret_cast<__half2*>(&u);
    return __half22float2(h);
}

__device__ __forceinline__ unsigned smem_u32(const void* p) {
    return (unsigned)__cvta_generic_to_shared(p);
}

__device__ __forceinline__ void mma16816(float* d,
                                         unsigned a0, unsigned a1, unsigned a2, unsigned a3,
                                         unsigned b0, unsigned b1) {
    asm volatile(
        "mma.sync.aligned.m16n8k16.row.col.f32.f16.f16.f32 "
        "{%0,%1,%2,%3}, {%4,%5,%6,%7}, {%8,%9}, {%0,%1,%2,%3};"
        : "+f"(d[0]), "+f"(d[1]), "+f"(d[2]), "+f"(d[3])
        : "r"(a0), "r"(a1), "r"(a2), "r"(a3), "r"(b0), "r"(b1));
}

// ---------------- tensor-core multi-output GEMM ----------------
// All NS weight sets staged ONCE per pass; X staged once per tile.
// CVT: convert fp32 input rows; else copy fp16 rows.
// TM: pass contains tm chain (zero s_pq per tile; final sigmoid accumulate into *tm_acc).
// flags: 1=relu, 2=scale(dinv), 4=fp16 gmem out, 8=block-diag W (Ws UL 32x64, Ws2 LR 32x64),
//        16=write outputs to sX2 (swizzled; col offset = osts[s]),
//        32=input from sX2 (syncthreads emitted before this spec),
//        64=tmred epilogue (dot w3 + atomics into s_pq)
template <int K, bool CVT, int NS, bool TM>
__device__ __forceinline__ void gemm_multi(
    const void* xin,
    const float* const* Ws, const float* const* Ws2, const float* const* Bs,
    void* const* Os, const int* osts, const unsigned* flg,
    int n, __half* sWh, __half* sXh, __half* sX2,
    float* s_pq, const float* s_w3c, float b3h, float b3e, float* tm_acc) {

    const int C = K / 8;          // 16B chunks per X row
    const int KP = K + 8;         // padded W row (halves)
    const int WSZ = 64 * KP;      // halves per weight spec
    int tid = threadIdx.x;
    int w = tid >> 5, lane = tid & 31;
    int node0 = (w & 7) * 16;     // 8 node groups x 16
    int o0 = (w >> 3) * 16;       // 4 out groups x 16
    int g = lane >> 2, t = lane & 3;
    int ntiles = (n + 127) >> 7;
    unsigned sx_base = smem_u32(sXh);
    unsigned sx2_base = TM ? smem_u32(sX2) : 0u;

    // ---- stage ALL weight specs once ----
    #pragma unroll
    for (int s = 0; s < NS; s++) {
        __half* sw = sWh + s * WSZ;
        if (flg[s] & 8u) {
            const float* Wh = Ws[s];
            const float* We = Ws2[s];
            for (int idx = tid; idx < 64 * (KP / 2); idx += NT) {
                int o = idx / (KP / 2), w2 = idx - o * (KP / 2);
                unsigned val = 0u;
                if (o < 32) {
                    if (w2 < 32) {
                        float2 v = *(const float2*)(Wh + o * 64 + w2 * 2);
                        __half2 h = __floats2half2_rn(v.x, v.y);
                        val = *reinterpret_cast<unsigned*>(&h);
                    }
                } else {
                    if (w2 >= 32 && w2 < 64) {
                        float2 v = *(const float2*)(We + (o - 32) * 64 + (w2 - 32) * 2);
                        __half2 h = __floats2half2_rn(v.x, v.y);
                        val = *reinterpret_cast<unsigned*>(&h);
                    }
                }
                *(unsigned*)(sw + o * KP + w2 * 2) = val;
            }
        } else {
            const float* Wp = Ws[s];
            for (int idx = tid; idx < 64 * (K / 2); idx += NT) {
                int o = idx / (K / 2), k2 = idx - o * (K / 2);
                float2 wv = *(const float2*)(Wp + o * K + k2 * 2);
                __half2 h = __floats2half2_rn(wv.x, wv.y);
                *(unsigned*)(sw + o * KP + k2 * 2) = *reinterpret_cast<unsigned*>(&h);
            }
        }
    }
    __syncthreads();

    for (int tile = blockIdx.x; tile < ntiles; tile += NB) {
        int base = tile << 7;
        int nn_max = n - base; if (nn_max > 128) nn_max = 128;
        __syncthreads();                              // prior tile's smem readers done
        if (TM) {
            if (tid < 256) s_pq[tid] = 0.f;
        }
        // ---- stage X ----
        if (CVT) {
            const float* xf = (const float*)xin;
            for (int idx = tid; idx < 128 * C; idx += NT) {
                int nn = idx / C, c = idx - nn * C;
                uint4 q;
                if (nn < nn_max) {
                    const float* p = xf + (size_t)(base + nn) * K + c * 8;
                    float4 v0 = *(const float4*)p;
                    float4 v1 = *(const float4*)(p + 4);
                    __half2 h0 = __floats2half2_rn(v0.x, v0.y);
                    __half2 h1 = __floats2half2_rn(v0.z, v0.w);
                    __half2 h2 = __floats2half2_rn(v1.x, v1.y);
                    __half2 h3 = __floats2half2_rn(v1.z, v1.w);
                    q.x = *reinterpret_cast<unsigned*>(&h0);
                    q.y = *reinterpret_cast<unsigned*>(&h1);
                    q.z = *reinterpret_cast<unsigned*>(&h2);
                    q.w = *reinterpret_cast<unsigned*>(&h3);
                } else { q = make_uint4(0, 0, 0, 0); }
                *(uint4*)(sXh + nn * K + ((c ^ (nn & 7)) << 3)) = q;
            }
        } else {
            const __half* xh = (const __half*)xin;
            for (int idx = tid; idx < 128 * C; idx += NT) {
                int nn = idx / C, c = idx - nn * C;
                uint4 q = (nn < nn_max)
                    ? *(const uint4*)(xh + (size_t)(base + nn) * K + c * 8)
                    : make_uint4(0, 0, 0, 0);
                *(uint4*)(sXh + nn * K + ((c ^ (nn & 7)) << 3)) = q;
            }
        }
        __syncthreads();

        // ---- compute all specs on the staged tile ----
        #pragma unroll
        for (int s = 0; s < NS; s++) {
            const __half* sw = sWh + s * WSZ;
            unsigned f = flg[s];
            if (f & 32u) __syncthreads();             // sX2 producers done
            const float* Bp = Bs[s];
            float ba0 = Bp[o0 + t * 2],     ba1 = Bp[o0 + t * 2 + 1];
            float bb0 = Bp[o0 + 8 + t * 2], bb1 = Bp[o0 + 8 + t * 2 + 1];
            float d0[4] = {ba0, ba1, ba0, ba1};
            float d1[4] = {bb0, bb1, bb0, bb1};

            unsigned xb = (TM && (f & 32u)) ? sx2_base : sx_base;
            int row = node0 + (lane & 15);
            #pragma unroll
            for (int ks = 0; ks < K / 16; ks++) {
                int chunk = ks * 2 + (lane >> 4);
                unsigned addr = xb + (unsigned)(row * (K * 2) + ((chunk ^ (row & 7)) << 4));
                unsigned a0, a1, a2, a3;
                asm volatile("ldmatrix.sync.aligned.m8n8.x4.shared.b16 {%0,%1,%2,%3}, [%4];"
                             : "=r"(a0), "=r"(a1), "=r"(a2), "=r"(a3) : "r"(addr));
                const __half* wb = sw + ks * 16 + t * 2;
                unsigned b00 = *(const unsigned*)(wb + (o0 + g) * KP);
                unsigned b01 = *(const unsigned*)(wb + (o0 + g) * KP + 8);
                unsigned b10 = *(const unsigned*)(wb + (o0 + 8 + g) * KP);
                unsigned b11 = *(const unsigned*)(wb + (o0 + 8 + g) * KP + 8);
                mma16816(d0, a0, a1, a2, a3, b00, b01);
                mma16816(d1, a0, a1, a2, a3, b10, b11);
            }

            int ost = osts[s];
            int nl0 = node0 + g, nl1 = nl0 + 8;
            #pragma unroll
            for (int half_ = 0; half_ < 2; half_++) {
                int nl = half_ ? nl1 : nl0;
                if (nl < nn_max) {
                    int node = base + nl;
                    float v0 = half_ ? d0[2] : d0[0];
                    float v1 = half_ ? d0[3] : d0[1];
                    float v2 = half_ ? d1[2] : d1[0];
                    float v3 = half_ ? d1[3] : d1[1];
                    if (f & 1u) {
                        v0 = fmaxf(v0, 0.f); v1 = fmaxf(v1, 0.f);
                        v2 = fmaxf(v2, 0.f); v3 = fmaxf(v3, 0.f);
                    }
                    if (f & 2u) {
                        float sc = d_dinv[node];
                        v0 *= sc; v1 *= sc; v2 *= sc; v3 *= sc;
                    }
                    if (TM && (f & 64u)) {
                        // dot with w3 slice; route to h-part (o0<32) or e-part
                        float c = v0 * s_w3c[o0 + t * 2] + v1 * s_w3c[o0 + t * 2 + 1]
                                + v2 * s_w3c[o0 + 8 + t * 2] + v3 * s_w3c[o0 + 8 + t * 2 + 1];
                        atomicAdd(&s_pq[(o0 < 32 ? 0 : 128) + nl], c);
                    } else if (TM && (f & 16u)) {
                        // write to sX2 (swizzled) at cols ost+o0(+8)+t*2
                        int c1 = ost + o0 + t * 2;
                        int c2 = c1 + 8;
                        __half2 h0 = __floats2half2_rn(v0, v1);
                        __half2 h1 = __floats2half2_rn(v2, v3);
                        int sw1 = nl * 128 + (((c1 >> 3) ^ (nl & 7)) << 3) + (c1 & 7);
                        int sw2 = nl * 128 + (((c2 >> 3) ^ (nl & 7)) << 3) + (c2 & 7);
                        *(unsigned*)(sX2 + sw1) = *reinterpret_cast<unsigned*>(&h0);
                        *(unsigned*)(sX2 + sw2) = *reinterpret_cast<unsigned*>(&h1);
                    } else if (f & 4u) {
                        __half* op = (__half*)Os[s] + (size_t)node * ost;
                        __half2 h0 = __floats2half2_rn(v0, v1);
                        __half2 h1 = __floats2half2_rn(v2, v3);
                        *(unsigned*)(op + o0 + t * 2)     = *reinterpret_cast<unsigned*>(&h0);
                        *(unsigned*)(op + o0 + 8 + t * 2) = *reinterpret_cast<unsigned*>(&h1);
                    } else {
                        float* op = (float*)Os[s] + (size_t)node * ost;
                        *(float2*)(op + o0 + t * 2)     = make_float2(v0, v1);
                        *(float2*)(op + o0 + 8 + t * 2) = make_float2(v2, v3);
                    }
                }
            }
        }

        if (TM) {
            __syncthreads();           // all tmred atomics done
            if (tid < 128 && tid < nn_max) {
                float ph = s_pq[tid], pe = s_pq[128 + tid];
                *tm_acc += 0.5f * (1.f / (1.f + expf(-(ph + b3h)))
                                 + 1.f / (1.f + expf(-(pe + b3e))));
            }
        }
    }
}

// ---------------- GCN aggregation (fp16 in/out), deg-loop unrolled x8 ----------------
template <int D>
__device__ void agg_stage(const __half* __restrict__ hs, __half* __restrict__ out, int n) {
    const int LPN = D / 4, NPW = 32 / LPN;
    int lane = threadIdx.x & 31;
    int gw = (blockIdx.x * NT + threadIdx.x) >> 5;
    const int TOTW = NB * (NT / 32);
    int sub = lane / LPN;
    int c = (lane % LPN) * 4;
    for (int b = gw; b * NPW < n; b += TOTW) {
        int node = b * NPW + sub;
        if (node < n) {
            uint2 us = *(const uint2*)(hs + (size_t)node * D + c);
            float2 f0 = h22f2(us.x), f1 = h22f2(us.y);
            float4 acc = make_float4(f0.x, f0.y, f1.x, f1.y);
            int j0 = d_off[node], j1 = d_off[node + 1];
            int j = j0;
            for (; j + 7 < j1; j += 8) {
                uint2 u[8];
                #pragma unroll
                for (int q = 0; q < 8; q++)
                    u[q] = *(const uint2*)(hs + (size_t)d_srcs[j + q] * D + c);
                #pragma unroll
                for (int q = 0; q < 8; q++) {
                    float2 a0 = h22f2(u[q].x), a1 = h22f2(u[q].y);
                    acc.x += a0.x; acc.y += a0.y; acc.z += a1.x; acc.w += a1.y;
                }
            }
            for (; j + 3 < j1; j += 4) {
                uint2 u[4];
                #pragma unroll
                for (int q = 0; q < 4; q++)
                    u[q] = *(const uint2*)(hs + (size_t)d_srcs[j + q] * D + c);
                #pragma unroll
                for (int q = 0; q < 4; q++) {
                    float2 a0 = h22f2(u[q].x), a1 = h22f2(u[q].y);
                    acc.x += a0.x; acc.y += a0.y; acc.z += a1.x; acc.w += a1.y;
                }
            }
            for (; j < j1; j++) {
                uint2 u0 = *(const uint2*)(hs + (size_t)d_srcs[j] * D + c);
                float2 a0 = h22f2(u0.x), a1 = h22f2(u0.y);
                acc.x += a0.x; acc.y += a0.y; acc.z += a1.x; acc.w += a1.y;
            }
            float dv = d_dinv[node];
            __half2 o0 = __floats2half2_rn(acc.x * dv, acc.y * dv);
            __half2 o1 = __floats2half2_rn(acc.z * dv, acc.w * dv);
            uint2 u;
            u.x = *reinterpret_cast<unsigned*>(&o0);
            u.y = *reinterpret_cast<unsigned*>(&o1);
            *(uint2*)(out + (size_t)node * D + c) = u;
        }
    }
}

// ---------------- the megakernel ----------------
extern __shared__ float smem_buf[];

__global__ __launch_bounds__(NT, 1) void mega(
    const float* __restrict__ x, const int* __restrict__ src, const int* __restrict__ dst,
    const float* __restrict__ pos,
    const float* __restrict__ emb_w, const float* __restrict__ emb_b,
    const float* __restrict__ c1_w, const float* __restrict__ c1_b,
    const float* __restrict__ c2_w, const float* __restrict__ c2_b,
    const float* __restrict__ bw1, const float* __restrict__ bb1,
    const float* __restrict__ bw2, const float* __restrict__ bb2,
    const float* __restrict__ hw1, const float* __restrict__ hb1,
    const float* __restrict__ hw2, const float* __restrict__ hb2,
    const float* __restrict__ hw3, const float* __restrict__ hb3,
    const float* __restrict__ ew1, const float* __restrict__ eb1,
    const float* __restrict__ ew2, const float* __restrict__ eb2,
    const float* __restrict__ ew3, const float* __restrict__ eb3,
    float* __restrict__ out, int n, int e) {

    __shared__ float s_red[32];
    __shared__ int   s_ired[32];
    __shared__ int   s_all[NB];
    __shared__ int   s_base;
    __shared__ float s_w3c[64];
    __shared__ float s_pq[256];

    int tid = threadIdx.x, bid = blockIdx.x;
    int lane = tid & 31, wid = tid >> 5;
    int gt = bid * NT + tid;
    const int GSTR = NB * NT;
    __half* sWh = (__half*)smem_buf;                     // up to 4 specs x [64][K+8] (69,632 B)
    __half* sXh = (__half*)((char*)smem_buf + 69632);    // [128][128] fp16 swizzled (32,768 B)
    __half* sX2 = (__half*)((char*)smem_buf + 102400);   // [128][128] fp16 swizzled (32,768 B)

    // ---- S1: count in-degrees (d_deg zero at entry) + bias staging ----
    for (int i = gt; i < e; i += GSTR) atomicAdd(&d_deg[dst[i]], 1);
    if (bid == 0 && tid < 64) d_b2c[tid] = (tid < 32) ? hb2[tid] : eb2[tid - 32];
    gbar();

    // ---- S2a: per-block chunk sums ----
    int chunk = (n + NB - 1) / NB;
    int lo = bid * chunk;
    int len = n - lo; if (len < 0) len = 0; if (len > chunk) len = chunk;
    int v = (tid < len) ? d_deg[lo + tid] : 0;
    {
        int wv = v;
        #pragma unroll
        for (int st = 16; st > 0; st >>= 1) wv += __shfl_down_sync(0xffffffffu, wv, st);
        if (lane == 0) s_ired[wid] = wv;
        __syncthreads();
        if (tid < 32) {
            int s = s_ired[tid];
            #pragma unroll
            for (int st = 16; st > 0; st >>= 1) s += __shfl_down_sync(0xffffffffu, s, st);
            if (tid == 0) d_bsum[bid] = s;
        }
    }
    gbar();

    // ---- S2c: base + local exclusive scan -> off/cur/dinv ----
    if (tid < NB) s_all[tid] = d_bsum[tid];
    __syncthreads();
    if (tid == 0) {
        int b = 0;
        for (int j = 0; j < bid; j++) b += s_all[j];
        s_base = b;
        if (bid == NB - 1) d_off[n] = b + s_all[NB - 1];
    }
    {
        int* a = (int*)smem_buf;
        a[tid] = v;
        __syncthreads();
        for (int st = 1; st < NT; st <<= 1) {
            int t = (tid >= st) ? a[tid - st] : 0;
            __syncthreads();
            a[tid] += t;
            __syncthreads();
        }
        int excl = a[tid] - v;
        if (tid < len) {
            int o = s_base + excl;
            d_off[lo + tid] = o;
            d_cur[lo + tid] = o;
            d_dinv[lo + tid] = rsqrtf((float)(v + 1));
        }
    }
    gbar();

    // ---- S3: CSR fill + re-zero deg (restores entry invariant) + emb GEMM ----
    for (int i = gt; i < e; i += GSTR) {
        int dd = dst[i];
        int p = atomicAdd(&d_cur[dd], 1);
        d_srcs[p] = src[i];
    }
    for (int i = gt; i < n; i += GSTR) d_deg[i] = 0;
    {
        const float* Ws[1] = {emb_w}; const float* Bs[1] = {emb_b};
        void* Os[1] = {(void*)d_h0h}; int ost[1] = {64}; unsigned fl[1] = {1u | 2u | 4u};
        gemm_multi<128, true, 1, false>(x, Ws, Ws, Bs, Os, ost, fl, n, sWh, sXh, sX2,
                                        nullptr, nullptr, 0.f, 0.f, nullptr);
    }
    gbar();

    // ---- S4: aggregate 64 ----
    agg_stage<64>(d_h0h, d_a0h, n);
    gbar();

    // ---- S5: GCN1 GEMM (64->128, relu, pre-scale) ----
    {
        const float* Ws[2] = {c1_w, c1_w + 64 * 64};
        const float* Bs[2] = {c1_b, c1_b + 64};
        void* Os[2] = {(void*)d_l1h, (void*)(d_l1h + 64)};
        int ost[2] = {128, 128}; unsigned fl[2] = {7u, 7u};
        gemm_multi<64, false, 2, false>(d_a0h, Ws, Ws, Bs, Os, ost, fl, n, sWh, sXh, sX2,
                                        nullptr, nullptr, 0.f, 0.f, nullptr);
    }
    gbar();

    // ---- S6: aggregate 128 ----
    agg_stage<128>(d_l1h, d_agh, n);
    gbar();

    // ---- S7: GCN2 GEMM (128->128, relu) ----
    {
        const float* Ws[2] = {c2_w, c2_w + 64 * 128};
        const float* Bs[2] = {c2_b, c2_b + 64};
        void* Os[2] = {(void*)d_l2h, (void*)(d_l2h + 64)};
        int ost[2] = {128, 128}; unsigned fl[2] = {1u | 4u, 1u | 4u};
        gemm_multi<128, false, 2, false>(d_agh, Ws, Ws, Bs, Os, ost, fl, n, sWh, sXh, sX2,
                                         nullptr, nullptr, 0.f, 0.f, nullptr);
    }
    gbar();

    // ---- S8: fused tail: g -> gmem; t1h/t1e -> sX2; t2 block-diag + w3/sigmoid reduce ----
    {
        if (tid < 64) s_w3c[tid] = (tid < 32) ? hw3[tid] : ew3[tid - 32];
        __syncthreads();
        float tmacc = 0.f;
        const float* Ws[4]  = {bw1, hw1, ew1, hw2};
        const float* W2s[4] = {bw1, hw1, ew1, ew2};
        const float* Bs[4]  = {bb1, hb1, eb1, (const float*)d_b2c};
        void* Os[4] = {(void*)d_gh, nullptr, nullptr, nullptr};
        int ost[4] = {64, 0, 64, 0};
        unsigned fl[4] = {4u, 1u | 16u, 1u | 16u, 1u | 8u | 32u | 64u};
        gemm_multi<128, false, 4, true>(d_l2h, Ws, W2s, Bs, Os, ost, fl, n, sWh, sXh, sX2,
                                        s_pq, s_w3c, hb3[0], eb3[0], &tmacc);
        // block-reduce tmacc (nonzero only on tid<128)
        __syncthreads();
        float tv = tmacc;
        #pragma unroll
        for (int st = 16; st > 0; st >>= 1) tv += __shfl_down_sync(0xffffffffu, tv, st);
        if (lane == 0) s_red[wid] = tv;
        __syncthreads();
        if (tid < 32) {
            float s = s_red[tid];
            #pragma unroll
            for (int st = 16; st > 0; st >>= 1) s += __shfl_down_sync(0xffffffffu, s, st);
            if (tid == 0) d_pt[bid] = (double)s;
        }
    }
    gbar();

    // ---- S9: bond energy (8 threads/edge, fp16 gathers of g) ----
    {
        int sub = tid & 7;
        float wreg[8];
        #pragma unroll
        for (int j = 0; j < 8; j++) wreg[j] = bw2[sub * 8 + j];
        float b2v = bb2[0];
        const int GROUPS = NB * (NT / 8);
        int g0 = (bid * NT + tid) >> 3;
        float accq = 0.f;
        int cnt = 0;
        for (int eid = g0; eid < e; eid += GROUPS) {
            int s = src[eid], d = dst[eid];
            uint4 us = *(const uint4*)(d_gh + (size_t)s * 64 + sub * 8);
            uint4 ud = *(const uint4*)(d_gh + (size_t)d * 64 + sub * 8);
            float2 s0 = h22f2(us.x), s1 = h22f2(us.y), s2 = h22f2(us.z), s3 = h22f2(us.w);
            float2 t0 = h22f2(ud.x), t1 = h22f2(ud.y), t2 = h22f2(ud.z), t3 = h22f2(ud.w);
            float p = 0.f;
            p += fmaxf(0.5f * (s0.x + t0.x), 0.f) * wreg[0];
            p += fmaxf(0.5f * (s0.y + t0.y), 0.f) * wreg[1];
            p += fmaxf(0.5f * (s1.x + t1.x), 0.f) * wreg[2];
            p += fmaxf(0.5f * (s1.y + t1.y), 0.f) * wreg[3];
            p += fmaxf(0.5f * (s2.x + t2.x), 0.f) * wreg[4];
            p += fmaxf(0.5f * (s2.y + t2.y), 0.f) * wreg[5];
            p += fmaxf(0.5f * (s3.x + t3.x), 0.f) * wreg[6];
            p += fmaxf(0.5f * (s3.y + t3.y), 0.f) * wreg[7];
            p += __shfl_down_sync(0xffffffffu, p, 4, 8);
            p += __shfl_down_sync(0xffffffffu, p, 2, 8);
            p += __shfl_down_sync(0xffffffffu, p, 1, 8);
            if (sub == 0) {
                float dx = pos[d * 3 + 0] - pos[s * 3 + 0];
                float dy = pos[d * 3 + 1] - pos[s * 3 + 1];
                float dz = pos[d * 3 + 2] - pos[s * 3 + 2];
                float L = sqrtf(dx * dx + dy * dy + dz * dz);
                float t = L - 1.5f;
                accq += p + 1000.f * t * t;
                cnt++;
            }
        }
        float vv = accq + b2v * (float)cnt;
        vv += __shfl_down_sync(0xffffffffu, vv, 16);
        vv += __shfl_down_sync(0xffffffffu, vv, 8);
        if (lane == 0) s_red[wid] = vv;
        __syncthreads();
        if (tid < 32) {
            float s = s_red[tid];
            #pragma unroll
            for (int st = 16; st > 0; st >>= 1) s += __shfl_down_sync(0xffffffffu, s, st);
            if (tid == 0) d_pb[bid] = (double)s;
        }
    }
    gbar();

    // ---- S10: final scalars (block 0) ----
    if (bid == 0) {
        double* db = (double*)smem_buf;
        if (tid < NB) { db[tid] = d_pb[tid]; db[NB + tid] = d_pt[tid]; }
        __syncthreads();
        if (tid == 0) {
            double eb = 0.0, tm = 0.0;
            for (int i = 0; i < NB; i++) { eb += db[i]; tm += db[NB + i]; }
            tm /= (double)n;
            double et = eb + 3.0;
            if (tm < 0.5) et += (1.0 - tm) * 10.0;
            out[0] = (float)eb;
            out[1] = 1.0f; out[2] = 1.0f; out[3] = 1.0f;
            out[4] = (float)et;
            out[5] = (float)tm;
        }
    }
}

// ---------------- host launcher: ONE kernel launch ----------------
extern "C" void kernel_launch(void* const* d_in, const int* in_sizes, int n_in,
                              void* d_out, int out_size) {
    const float* x     = (const float*)d_in[0];
    const int*   ei    = (const int*)  d_in[1];
    const float* pos   = (const float*)d_in[2];
    /* d_in[3] = batch (unused) */
    const float* emb_w = (const float*)d_in[4];
    const float* emb_b = (const float*)d_in[5];
    const float* c1_w  = (const float*)d_in[6];
    const float* c1_b  = (const float*)d_in[7];
    const float* c2_w  = (const float*)d_in[8];
    const float* c2_b  = (const float*)d_in[9];
    const float* bw1   = (const float*)d_in[10];
    const float* bb1   = (const float*)d_in[11];
    const float* bw2   = (const float*)d_in[12];
    const float* bb2   = (const float*)d_in[13];
    const float* hw1   = (const float*)d_in[14];
    const float* hb1   = (const float*)d_in[15];
    const float* hw2   = (const float*)d_in[16];
    const float* hb2   = (const float*)d_in[17];
    const float* hw3   = (const float*)d_in[18];
    const float* hb3   = (const float*)d_in[19];
    const float* ew1   = (const float*)d_in[20];
    const float* eb1   = (const float*)d_in[21];
    const float* ew2   = (const float*)d_in[22];
    const float* eb2   = (const float*)d_in[23];
    const float* ew3   = (const float*)d_in[24];
    const float* eb3   = (const float*)d_in[25];

    int n = in_sizes[0] / 128;
    int e = in_sizes[1] / 2;
    const int* src = ei;
    const int* dst = ei + e;
    float* out = (float*)d_out;

    const int SMEM = 69632 + 32768 + 32768;   // 4x sW fp16 [64][136] + sX + sX2 = 135,168 B
    cudaFuncSetAttribute((const void*)mega, cudaFuncAttributeMaxDynamicSharedMemorySize, SMEM);

    mega<<<NB, NT, SMEM>>>(x, src, dst, pos,
                           emb_w, emb_b, c1_w, c1_b, c2_w, c2_b,
                           bw1, bb1, bw2, bb2,
                           hw1, hb1, hw2, hb2, hw3, hb3,
                           ew1, eb1, ew2, eb2, ew3, eb3,
                           out, n, e);
}

// round 17
// speedup vs baseline: 1.1515x; 1.0536x over previous
#include <cuda_runtime.h>
#include <cuda_fp16.h>
#include <math.h>

#define NB 148
#define NT 1024
#define NMAX 50000
#define EMAX 1600000
#define SLOTS 128

typedef unsigned long long u64;

// ---------------- scratch (device globals) ----------------
__device__ __half d_h0h[(size_t)NMAX * 64];   // emb out (pre-scaled by dinv), fp16
__device__ __half d_a0h[(size_t)NMAX * 64];   // aggregated 64, fp16
__device__ __half d_l1h[(size_t)NMAX * 128];  // c1 out (pre-scaled), fp16
__device__ __half d_agh[(size_t)NMAX * 128];  // aggregated 128, fp16
__device__ __half d_l2h[(size_t)NMAX * 128];  // c2 out = final features, fp16
__device__ __half d_gh [(size_t)NMAX * 64];   // bond projection, fp16
__device__ float  d_b2c[64];                  // [hb2 | eb2]
__device__ int    d_deg[NMAX];                // ZERO invariant at kernel entry (re-zeroed each call)
__device__ int    d_slot[(size_t)NMAX * SLOTS]; // padded adjacency (src lists per dst)
__device__ double d_pb[NB];
__device__ double d_pt[NB];
__device__ unsigned int g_bar;               // monotonic across replays

// ---------------- grid barrier ----------------
__device__ __forceinline__ void gbar() {
    __syncthreads();
    if (threadIdx.x == 0) {
        __threadfence();
        unsigned int old = atomicAdd(&g_bar, 1u);
        unsigned int target = (old / NB + 1u) * NB;
        while (*((volatile unsigned int*)&g_bar) < target) { }
        __threadfence();
    }
    __syncthreads();
}

__device__ __forceinline__ float2 h22f2(unsigned u) {
    __half2 h = *reinterpret_cast<__half2*>(&u);
    return __half22float2(h);
}

__device__ __forceinline__ unsigned smem_u32(const void* p) {
    return (unsigned)__cvta_generic_to_shared(p);
}

__device__ __forceinline__ void mma16816(float* d,
                                         unsigned a0, unsigned a1, unsigned a2, unsigned a3,
                                         unsigned b0, unsigned b1) {
    asm volatile(
        "mma.sync.aligned.m16n8k16.row.col.f32.f16.f16.f32 "
        "{%0,%1,%2,%3}, {%4,%5,%6,%7}, {%8,%9}, {%0,%1,%2,%3};"
        : "+f"(d[0]), "+f"(d[1]), "+f"(d[2]), "+f"(d[3])
        : "r"(a0), "r"(a1), "r"(a2), "r"(a3), "r"(b0), "r"(b1));
}

// ---------------- tensor-core multi-output GEMM ----------------
// All NS weight sets staged ONCE per pass; X staged once per tile.
// CVT: convert fp32 input rows; else copy fp16 rows.
// TM: pass contains tm chain (zero s_pq per tile; final sigmoid accumulate into *tm_acc).
// flags: 1=relu, 2=scale(on-the-fly dinv from d_deg), 4=fp16 gmem out, 8=block-diag W,
//        16=write outputs to sX2, 32=input from sX2 (sync before), 64=tmred epilogue
template <int K, bool CVT, int NS, bool TM>
__device__ __forceinline__ void gemm_multi(
    const void* xin,
    const float* const* Ws, const float* const* Ws2, const float* const* Bs,
    void* const* Os, const int* osts, const unsigned* flg,
    int n, __half* sWh, __half* sXh, __half* sX2,
    float* s_pq, const float* s_w3c, float b3h, float b3e, float* tm_acc) {

    const int C = K / 8;          // 16B chunks per X row
    const int KP = K + 8;         // padded W row (halves)
    const int WSZ = 64 * KP;      // halves per weight spec
    int tid = threadIdx.x;
    int w = tid >> 5, lane = tid & 31;
    int node0 = (w & 7) * 16;     // 8 node groups x 16
    int o0 = (w >> 3) * 16;       // 4 out groups x 16
    int g = lane >> 2, t = lane & 3;
    int ntiles = (n + 127) >> 7;
    unsigned sx_base = smem_u32(sXh);
    unsigned sx2_base = TM ? smem_u32(sX2) : 0u;

    // ---- stage ALL weight specs once ----
    #pragma unroll
    for (int s = 0; s < NS; s++) {
        __half* sw = sWh + s * WSZ;
        if (flg[s] & 8u) {
            const float* Wh = Ws[s];
            const float* We = Ws2[s];
            for (int idx = tid; idx < 64 * (KP / 2); idx += NT) {
                int o = idx / (KP / 2), w2 = idx - o * (KP / 2);
                unsigned val = 0u;
                if (o < 32) {
                    if (w2 < 32) {
                        float2 v = *(const float2*)(Wh + o * 64 + w2 * 2);
                        __half2 h = __floats2half2_rn(v.x, v.y);
                        val = *reinterpret_cast<unsigned*>(&h);
                    }
                } else {
                    if (w2 >= 32 && w2 < 64) {
                        float2 v = *(const float2*)(We + (o - 32) * 64 + (w2 - 32) * 2);
                        __half2 h = __floats2half2_rn(v.x, v.y);
                        val = *reinterpret_cast<unsigned*>(&h);
                    }
                }
                *(unsigned*)(sw + o * KP + w2 * 2) = val;
            }
        } else {
            const float* Wp = Ws[s];
            for (int idx = tid; idx < 64 * (K / 2); idx += NT) {
                int o = idx / (K / 2), k2 = idx - o * (K / 2);
                float2 wv = *(const float2*)(Wp + o * K + k2 * 2);
                __half2 h = __floats2half2_rn(wv.x, wv.y);
                *(unsigned*)(sw + o * KP + k2 * 2) = *reinterpret_cast<unsigned*>(&h);
            }
        }
    }
    __syncthreads();

    for (int tile = blockIdx.x; tile < ntiles; tile += NB) {
        int base = tile << 7;
        int nn_max = n - base; if (nn_max > 128) nn_max = 128;
        __syncthreads();                              // prior tile's smem readers done
        if (TM) {
            if (tid < 256) s_pq[tid] = 0.f;
        }
        // ---- stage X ----
        if (CVT) {
            const float* xf = (const float*)xin;
            for (int idx = tid; idx < 128 * C; idx += NT) {
                int nn = idx / C, c = idx - nn * C;
                uint4 q;
                if (nn < nn_max) {
                    const float* p = xf + (size_t)(base + nn) * K + c * 8;
                    float4 v0 = *(const float4*)p;
                    float4 v1 = *(const float4*)(p + 4);
                    __half2 h0 = __floats2half2_rn(v0.x, v0.y);
                    __half2 h1 = __floats2half2_rn(v0.z, v0.w);
                    __half2 h2 = __floats2half2_rn(v1.x, v1.y);
                    __half2 h3 = __floats2half2_rn(v1.z, v1.w);
                    q.x = *reinterpret_cast<unsigned*>(&h0);
                    q.y = *reinterpret_cast<unsigned*>(&h1);
                    q.z = *reinterpret_cast<unsigned*>(&h2);
                    q.w = *reinterpret_cast<unsigned*>(&h3);
                } else { q = make_uint4(0, 0, 0, 0); }
                *(uint4*)(sXh + nn * K + ((c ^ (nn & 7)) << 3)) = q;
            }
        } else {
            const __half* xh = (const __half*)xin;
            for (int idx = tid; idx < 128 * C; idx += NT) {
                int nn = idx / C, c = idx - nn * C;
                uint4 q = (nn < nn_max)
                    ? *(const uint4*)(xh + (size_t)(base + nn) * K + c * 8)
                    : make_uint4(0, 0, 0, 0);
                *(uint4*)(sXh + nn * K + ((c ^ (nn & 7)) << 3)) = q;
            }
        }
        __syncthreads();

        // ---- compute all specs on the staged tile ----
        #pragma unroll
        for (int s = 0; s < NS; s++) {
            const __half* sw = sWh + s * WSZ;
            unsigned f = flg[s];
            if (f & 32u) __syncthreads();             // sX2 producers done
            const float* Bp = Bs[s];
            float ba0 = Bp[o0 + t * 2],     ba1 = Bp[o0 + t * 2 + 1];
            float bb0 = Bp[o0 + 8 + t * 2], bb1 = Bp[o0 + 8 + t * 2 + 1];
            float d0[4] = {ba0, ba1, ba0, ba1};
            float d1[4] = {bb0, bb1, bb0, bb1};

            unsigned xb = (TM && (f & 32u)) ? sx2_base : sx_base;
            int row = node0 + (lane & 15);
            #pragma unroll
            for (int ks = 0; ks < K / 16; ks++) {
                int chunk = ks * 2 + (lane >> 4);
                unsigned addr = xb + (unsigned)(row * (K * 2) + ((chunk ^ (row & 7)) << 4));
                unsigned a0, a1, a2, a3;
                asm volatile("ldmatrix.sync.aligned.m8n8.x4.shared.b16 {%0,%1,%2,%3}, [%4];"
                             : "=r"(a0), "=r"(a1), "=r"(a2), "=r"(a3) : "r"(addr));
                const __half* wb = sw + ks * 16 + t * 2;
                unsigned b00 = *(const unsigned*)(wb + (o0 + g) * KP);
                unsigned b01 = *(const unsigned*)(wb + (o0 + g) * KP + 8);
                unsigned b10 = *(const unsigned*)(wb + (o0 + 8 + g) * KP);
                unsigned b11 = *(const unsigned*)(wb + (o0 + 8 + g) * KP + 8);
                mma16816(d0, a0, a1, a2, a3, b00, b01);
                mma16816(d1, a0, a1, a2, a3, b10, b11);
            }

            int ost = osts[s];
            int nl0 = node0 + g, nl1 = nl0 + 8;
            #pragma unroll
            for (int half_ = 0; half_ < 2; half_++) {
                int nl = half_ ? nl1 : nl0;
                if (nl < nn_max) {
                    int node = base + nl;
                    float v0 = half_ ? d0[2] : d0[0];
                    float v1 = half_ ? d0[3] : d0[1];
                    float v2 = half_ ? d1[2] : d1[0];
                    float v3 = half_ ? d1[3] : d1[1];
                    if (f & 1u) {
                        v0 = fmaxf(v0, 0.f); v1 = fmaxf(v1, 0.f);
                        v2 = fmaxf(v2, 0.f); v3 = fmaxf(v3, 0.f);
                    }
                    if (f & 2u) {
                        float sc = rsqrtf((float)(d_deg[node] + 1));
                        v0 *= sc; v1 *= sc; v2 *= sc; v3 *= sc;
                    }
                    if (TM && (f & 64u)) {
                        float c = v0 * s_w3c[o0 + t * 2] + v1 * s_w3c[o0 + t * 2 + 1]
                                + v2 * s_w3c[o0 + 8 + t * 2] + v3 * s_w3c[o0 + 8 + t * 2 + 1];
                        atomicAdd(&s_pq[(o0 < 32 ? 0 : 128) + nl], c);
                    } else if (TM && (f & 16u)) {
                        int c1 = ost + o0 + t * 2;
                        int c2 = c1 + 8;
                        __half2 h0 = __floats2half2_rn(v0, v1);
                        __half2 h1 = __floats2half2_rn(v2, v3);
                        int sw1 = nl * 128 + (((c1 >> 3) ^ (nl & 7)) << 3) + (c1 & 7);
                        int sw2 = nl * 128 + (((c2 >> 3) ^ (nl & 7)) << 3) + (c2 & 7);
                        *(unsigned*)(sX2 + sw1) = *reinterpret_cast<unsigned*>(&h0);
                        *(unsigned*)(sX2 + sw2) = *reinterpret_cast<unsigned*>(&h1);
                    } else if (f & 4u) {
                        __half* op = (__half*)Os[s] + (size_t)node * ost;
                        __half2 h0 = __floats2half2_rn(v0, v1);
                        __half2 h1 = __floats2half2_rn(v2, v3);
                        *(unsigned*)(op + o0 + t * 2)     = *reinterpret_cast<unsigned*>(&h0);
                        *(unsigned*)(op + o0 + 8 + t * 2) = *reinterpret_cast<unsigned*>(&h1);
                    } else {
                        float* op = (float*)Os[s] + (size_t)node * ost;
                        *(float2*)(op + o0 + t * 2)     = make_float2(v0, v1);
                        *(float2*)(op + o0 + 8 + t * 2) = make_float2(v2, v3);
                    }
                }
            }
        }

        if (TM) {
            __syncthreads();           // all tmred atomics done
            if (tid < 128 && tid < nn_max) {
                float ph = s_pq[tid], pe = s_pq[128 + tid];
                *tm_acc += 0.5f * (1.f / (1.f + expf(-(ph + b3h)))
                                 + 1.f / (1.f + expf(-(pe + b3e))));
            }
        }
    }
}

// ---------------- GCN aggregation (fp16 in/out), slot adjacency, deg-loop unrolled x8 ----
template <int D>
__device__ void agg_stage(const __half* __restrict__ hs, __half* __restrict__ out, int n) {
    const int LPN = D / 4, NPW = 32 / LPN;
    int lane = threadIdx.x & 31;
    int gw = (blockIdx.x * NT + threadIdx.x) >> 5;
    const int TOTW = NB * (NT / 32);
    int sub = lane / LPN;
    int c = (lane % LPN) * 4;
    for (int b = gw; b * NPW < n; b += TOTW) {
        int node = b * NPW + sub;
        if (node < n) {
            uint2 us = *(const uint2*)(hs + (size_t)node * D + c);
            float2 f0 = h22f2(us.x), f1 = h22f2(us.y);
            float4 acc = make_float4(f0.x, f0.y, f1.x, f1.y);
            int deg = d_deg[node];
            const int* sl = d_slot + (size_t)node * SLOTS;
            int j = 0;
            for (; j + 7 < deg; j += 8) {
                uint2 u[8];
                #pragma unroll
                for (int q = 0; q < 8; q++)
                    u[q] = *(const uint2*)(hs + (size_t)sl[j + q] * D + c);
                #pragma unroll
                for (int q = 0; q < 8; q++) {
                    float2 a0 = h22f2(u[q].x), a1 = h22f2(u[q].y);
                    acc.x += a0.x; acc.y += a0.y; acc.z += a1.x; acc.w += a1.y;
                }
            }
            for (; j + 3 < deg; j += 4) {
                uint2 u[4];
                #pragma unroll
                for (int q = 0; q < 4; q++)
                    u[q] = *(const uint2*)(hs + (size_t)sl[j + q] * D + c);
                #pragma unroll
                for (int q = 0; q < 4; q++) {
                    float2 a0 = h22f2(u[q].x), a1 = h22f2(u[q].y);
                    acc.x += a0.x; acc.y += a0.y; acc.z += a1.x; acc.w += a1.y;
                }
            }
            for (; j < deg; j++) {
                uint2 u0 = *(const uint2*)(hs + (size_t)sl[j] * D + c);
                float2 a0 = h22f2(u0.x), a1 = h22f2(u0.y);
                acc.x += a0.x; acc.y += a0.y; acc.z += a1.x; acc.w += a1.y;
            }
            float dv = rsqrtf((float)(deg + 1));
            __half2 o0 = __floats2half2_rn(acc.x * dv, acc.y * dv);
            __half2 o1 = __floats2half2_rn(acc.z * dv, acc.w * dv);
            uint2 u;
            u.x = *reinterpret_cast<unsigned*>(&o0);
            u.y = *reinterpret_cast<unsigned*>(&o1);
            *(uint2*)(out + (size_t)node * D + c) = u;
        }
    }
}

// ---------------- the megakernel ----------------
extern __shared__ float smem_buf[];

__global__ __launch_bounds__(NT, 1) void mega(
    const float* __restrict__ x, const int* __restrict__ src, const int* __restrict__ dst,
    const float* __restrict__ pos,
    const float* __restrict__ emb_w, const float* __restrict__ emb_b,
    const float* __restrict__ c1_w, const float* __restrict__ c1_b,
    const float* __restrict__ c2_w, const float* __restrict__ c2_b,
    const float* __restrict__ bw1, const float* __restrict__ bb1,
    const float* __restrict__ bw2, const float* __restrict__ bb2,
    const float* __restrict__ hw1, const float* __restrict__ hb1,
    const float* __restrict__ hw2, const float* __restrict__ hb2,
    const float* __restrict__ hw3, const float* __restrict__ hb3,
    const float* __restrict__ ew1, const float* __restrict__ eb1,
    const float* __restrict__ ew2, const float* __restrict__ eb2,
    const float* __restrict__ ew3, const float* __restrict__ eb3,
    float* __restrict__ out, int n, int e) {

    __shared__ float s_red[32];
    __shared__ float s_w3c[64];
    __shared__ float s_pq[256];

    int tid = threadIdx.x, bid = blockIdx.x;
    int lane = tid & 31, wid = tid >> 5;
    int gt = bid * NT + tid;
    const int GSTR = NB * NT;
    __half* sWh = (__half*)smem_buf;                     // up to 4 specs x [64][K+8] (69,632 B)
    __half* sXh = (__half*)((char*)smem_buf + 69632);    // [128][128] fp16 swizzled (32,768 B)
    __half* sX2 = (__half*)((char*)smem_buf + 102400);   // [128][128] fp16 swizzled (32,768 B)

    // ---- S1: fused count+fill into slot adjacency (d_deg zero at entry) + bias staging ----
    for (int i = gt; i < e; i += GSTR) {
        int dd = dst[i];
        int p = atomicAdd(&d_deg[dd], 1);
        d_slot[(size_t)dd * SLOTS + p] = src[i];
    }
    if (bid == 0 && tid < 64) d_b2c[tid] = (tid < 32) ? hb2[tid] : eb2[tid - 32];
    gbar();

    // ---- S2: embedding GEMM (fp32 x converted at staging; dinv on the fly) ----
    {
        const float* Ws[1] = {emb_w}; const float* Bs[1] = {emb_b};
        void* Os[1] = {(void*)d_h0h}; int ost[1] = {64}; unsigned fl[1] = {1u | 2u | 4u};
        gemm_multi<128, true, 1, false>(x, Ws, Ws, Bs, Os, ost, fl, n, sWh, sXh, sX2,
                                        nullptr, nullptr, 0.f, 0.f, nullptr);
    }
    gbar();

    // ---- S3: aggregate 64 ----
    agg_stage<64>(d_h0h, d_a0h, n);
    gbar();

    // ---- S4: GCN1 GEMM (64->128, relu, pre-scale) ----
    {
        const float* Ws[2] = {c1_w, c1_w + 64 * 64};
        const float* Bs[2] = {c1_b, c1_b + 64};
        void* Os[2] = {(void*)d_l1h, (void*)(d_l1h + 64)};
        int ost[2] = {128, 128}; unsigned fl[2] = {7u, 7u};
        gemm_multi<64, false, 2, false>(d_a0h, Ws, Ws, Bs, Os, ost, fl, n, sWh, sXh, sX2,
                                        nullptr, nullptr, 0.f, 0.f, nullptr);
    }
    gbar();

    // ---- S5: aggregate 128 (last deg use) ----
    agg_stage<128>(d_l1h, d_agh, n);
    gbar();

    // ---- S6: GCN2 GEMM (128->128, relu) + re-zero deg (restores entry invariant) ----
    for (int i = gt; i < n; i += GSTR) d_deg[i] = 0;
    {
        const float* Ws[2] = {c2_w, c2_w + 64 * 128};
        const float* Bs[2] = {c2_b, c2_b + 64};
        void* Os[2] = {(void*)d_l2h, (void*)(d_l2h + 64)};
        int ost[2] = {128, 128}; unsigned fl[2] = {1u | 4u, 1u | 4u};
        gemm_multi<128, false, 2, false>(d_agh, Ws, Ws, Bs, Os, ost, fl, n, sWh, sXh, sX2,
                                         nullptr, nullptr, 0.f, 0.f, nullptr);
    }
    gbar();

    // ---- S7: fused tail: g -> gmem; t1h/t1e -> sX2; t2 block-diag + w3/sigmoid reduce ----
    {
        if (tid < 64) s_w3c[tid] = (tid < 32) ? hw3[tid] : ew3[tid - 32];
        __syncthreads();
        float tmacc = 0.f;
        const float* Ws[4]  = {bw1, hw1, ew1, hw2};
        const float* W2s[4] = {bw1, hw1, ew1, ew2};
        const float* Bs[4]  = {bb1, hb1, eb1, (const float*)d_b2c};
        void* Os[4] = {(void*)d_gh, nullptr, nullptr, nullptr};
        int ost[4] = {64, 0, 64, 0};
        unsigned fl[4] = {4u, 1u | 16u, 1u | 16u, 1u | 8u | 32u | 64u};
        gemm_multi<128, false, 4, true>(d_l2h, Ws, W2s, Bs, Os, ost, fl, n, sWh, sXh, sX2,
                                        s_pq, s_w3c, hb3[0], eb3[0], &tmacc);
        // block-reduce tmacc (nonzero only on tid<128)
        __syncthreads();
        float tv = tmacc;
        #pragma unroll
        for (int st = 16; st > 0; st >>= 1) tv += __shfl_down_sync(0xffffffffu, tv, st);
        if (lane == 0) s_red[wid] = tv;
        __syncthreads();
        if (tid < 32) {
            float s = s_red[tid];
            #pragma unroll
            for (int st = 16; st > 0; st >>= 1) s += __shfl_down_sync(0xffffffffu, s, st);
            if (tid == 0) d_pt[bid] = (double)s;
        }
    }
    gbar();

    // ---- S8: bond energy (8 threads/edge, fp16 gathers of g) ----
    {
        int sub = tid & 7;
        float wreg[8];
        #pragma unroll
        for (int j = 0; j < 8; j++) wreg[j] = bw2[sub * 8 + j];
        float b2v = bb2[0];
        const int GROUPS = NB * (NT / 8);
        int g0 = (bid * NT + tid) >> 3;
        float accq = 0.f;
        int cnt = 0;
        for (int eid = g0; eid < e; eid += GROUPS) {
            int s = src[eid], d = dst[eid];
            uint4 us = *(const uint4*)(d_gh + (size_t)s * 64 + sub * 8);
            uint4 ud = *(const uint4*)(d_gh + (size_t)d * 64 + sub * 8);
            float2 s0 = h22f2(us.x), s1 = h22f2(us.y), s2 = h22f2(us.z), s3 = h22f2(us.w);
            float2 t0 = h22f2(ud.x), t1 = h22f2(ud.y), t2 = h22f2(ud.z), t3 = h22f2(ud.w);
            float p = 0.f;
            p += fmaxf(0.5f * (s0.x + t0.x), 0.f) * wreg[0];
            p += fmaxf(0.5f * (s0.y + t0.y), 0.f) * wreg[1];
            p += fmaxf(0.5f * (s1.x + t1.x), 0.f) * wreg[2];
            p += fmaxf(0.5f * (s1.y + t1.y), 0.f) * wreg[3];
            p += fmaxf(0.5f * (s2.x + t2.x), 0.f) * wreg[4];
            p += fmaxf(0.5f * (s2.y + t2.y), 0.f) * wreg[5];
            p += fmaxf(0.5f * (s3.x + t3.x), 0.f) * wreg[6];
            p += fmaxf(0.5f * (s3.y + t3.y), 0.f) * wreg[7];
            p += __shfl_down_sync(0xffffffffu, p, 4, 8);
            p += __shfl_down_sync(0xffffffffu, p, 2, 8);
            p += __shfl_down_sync(0xffffffffu, p, 1, 8);
            if (sub == 0) {
                float dx = pos[d * 3 + 0] - pos[s * 3 + 0];
                float dy = pos[d * 3 + 1] - pos[s * 3 + 1];
                float dz = pos[d * 3 + 2] - pos[s * 3 + 2];
                float L = sqrtf(dx * dx + dy * dy + dz * dz);
                float t = L - 1.5f;
                accq += p + 1000.f * t * t;
                cnt++;
            }
        }
        float vv = accq + b2v * (float)cnt;
        vv += __shfl_down_sync(0xffffffffu, vv, 16);
        vv += __shfl_down_sync(0xffffffffu, vv, 8);
        if (lane == 0) s_red[wid] = vv;
        __syncthreads();
        if (tid < 32) {
            float s = s_red[tid];
            #pragma unroll
            for (int st = 16; st > 0; st >>= 1) s += __shfl_down_sync(0xffffffffu, s, st);
            if (tid == 0) d_pb[bid] = (double)s;
        }
    }
    gbar();

    // ---- S9: final scalars (block 0) ----
    if (bid == 0) {
        double* db = (double*)smem_buf;
        if (tid < NB) { db[tid] = d_pb[tid]; db[NB + tid] = d_pt[tid]; }
        __syncthreads();
        if (tid == 0) {
            double eb = 0.0, tm = 0.0;
            for (int i = 0; i < NB; i++) { eb += db[i]; tm += db[NB + i]; }
            tm /= (double)n;
            double et = eb + 3.0;
            if (tm < 0.5) et += (1.0 - tm) * 10.0;
            out[0] = (float)eb;
            out[1] = 1.0f; out[2] = 1.0f; out[3] = 1.0f;
            out[4] = (float)et;
            out[5] = (float)tm;
        }
    }
}

// ---------------- host launcher: ONE kernel launch ----------------
extern "C" void kernel_launch(void* const* d_in, const int* in_sizes, int n_in,
                              void* d_out, int out_size) {
    const float* x     = (const float*)d_in[0];
    const int*   ei    = (const int*)  d_in[1];
    const float* pos   = (const float*)d_in[2];
    /* d_in[3] = batch (unused) */
    const float* emb_w = (const float*)d_in[4];
    const float* emb_b = (const float*)d_in[5];
    const float* c1_w  = (const float*)d_in[6];
    const float* c1_b  = (const float*)d_in[7];
    const float* c2_w  = (const float*)d_in[8];
    const float* c2_b  = (const float*)d_in[9];
    const float* bw1   = (const float*)d_in[10];
    const float* bb1   = (const float*)d_in[11];
    const float* bw2   = (const float*)d_in[12];
    const float* bb2   = (const float*)d_in[13];
    const float* hw1   = (const float*)d_in[14];
    const float* hb1   = (const float*)d_in[15];
    const float* hw2   = (const float*)d_in[16];
    const float* hb2   = (const float*)d_in[17];
    const float* hw3   = (const float*)d_in[18];
    const float* hb3   = (const float*)d_in[19];
    const float* ew1   = (const float*)d_in[20];
    const float* eb1   = (const float*)d_in[21];
    const float* ew2   = (const float*)d_in[22];
    const float* eb2   = (const float*)d_in[23];
    const float* ew3   = (const float*)d_in[24];
    const float* eb3   = (const float*)d_in[25];

    int n = in_sizes[0] / 128;
    int e = in_sizes[1] / 2;
    const int* src = ei;
    const int* dst = ei + e;
    float* out = (float*)d_out;

    const int SMEM = 69632 + 32768 + 32768;   // 4x sW fp16 [64][136] + sX + sX2 = 135,168 B
    cudaFuncSetAttribute((const void*)mega, cudaFuncAttributeMaxDynamicSharedMemorySize, SMEM);

    mega<<<NB, NT, SMEM>>>(x, src, dst, pos,
                           emb_w, emb_b, c1_w, c1_b, c2_w, c2_b,
                           bw1, bb1, bw2, bb2,
                           hw1, hb1, hw2, hb2, hw3, hb3,
                           ew1, eb1, ew2, eb2, ew3, eb3,
                           out, n, e);
}